// round 13
// baseline (speedup 1.0000x reference)
#include <cuda_runtime.h>
#include <cuda_bf16.h>
#include <cuda_fp16.h>
#include <math.h>
#include <stdint.h>

#define N_NODES 50000
#define N_EDGES 800000
#define F_INN   512
#define HID     128
#define N_CLS   40
#define EPS_V   0.3f

#define CGRID   196
#define AGRID   888              // 6/SM x 148 = all resident
#define AWARPS  (AGRID * 8)

// ---------------- scratch (static device globals; no allocations) ----------
__device__ float  g_raw[N_NODES * HID];
__device__ __half g_hA [N_NODES * HID];
__device__ __half g_hB [N_NODES * HID];
__device__ float  g_pA [N_NODES];
__device__ float  g_qA [N_NODES];
__device__ float  g_pB [N_NODES];
__device__ float  g_qB [N_NODES];
__device__ float  g_nd [N_NODES];
__device__ float  g_ew [N_EDGES];
__device__ int    g_esrc[N_EDGES];
__device__ int    g_indptr[N_NODES + 1];
__device__ int    g_cnt[N_NODES];
__device__ int    g_deg[N_NODES];
__device__ int    g_cursor[N_NODES];
__device__ int    g_bsum[256];
__device__ int    g_boff[256];
__device__ int    g_bars[4];     // [0]=csr, [1]=agg (monotonic counters)
__device__ uint16_t g_whi[HID * F_INN];
__device__ uint16_t g_wlo[HID * F_INN];

// ================= PTX helpers (baseline sm_80+ PTX only) =================
__device__ __forceinline__ uint32_t smem_u32(const void* p) {
    uint32_t a;
    asm("{ .reg .u64 t; cvta.to.shared.u64 t, %1; cvt.u32.u64 %0, t; }" : "=r"(a) : "l"(p));
    return a;
}
__device__ __forceinline__ void ldsm_x4(uint32_t (&r)[4], uint32_t addr) {
    asm volatile("ldmatrix.sync.aligned.m8n8.x4.shared.b16 {%0,%1,%2,%3}, [%4];"
        : "=r"(r[0]), "=r"(r[1]), "=r"(r[2]), "=r"(r[3]) : "r"(addr));
}
__device__ __forceinline__ void ldsm_x2(uint32_t (&r)[2], uint32_t addr) {
    asm volatile("ldmatrix.sync.aligned.m8n8.x2.shared.b16 {%0,%1}, [%2];"
        : "=r"(r[0]), "=r"(r[1]) : "r"(addr));
}
__device__ __forceinline__ void mma_bf16(float (&d)[4], const uint32_t (&a)[4], const uint32_t (&b)[2]) {
    asm volatile("mma.sync.aligned.m16n8k16.row.col.f32.bf16.bf16.f32 "
        "{%0,%1,%2,%3}, {%4,%5,%6,%7}, {%8,%9}, {%0,%1,%2,%3};"
        : "+f"(d[0]), "+f"(d[1]), "+f"(d[2]), "+f"(d[3])
        : "r"(a[0]), "r"(a[1]), "r"(a[2]), "r"(a[3]), "r"(b[0]), "r"(b[1]));
}
__device__ __forceinline__ void cp_async16(uint32_t saddr, const void* gaddr) {
    asm volatile("cp.async.cg.shared.global [%0], [%1], 16;" :: "r"(saddr), "l"(gaddr));
}
#define CP_COMMIT() asm volatile("cp.async.commit_group;" ::: "memory")
#define CP_WAIT(N)  asm volatile("cp.async.wait_group %0;" :: "n"(N) : "memory")

__device__ __forceinline__ uint32_t pack_bf16lo(float x, float y) {
    __nv_bfloat162 t = __floats2bfloat162_rn(x, y);
    return *reinterpret_cast<uint32_t*>(&t);
}

// monotonic grid barrier. __threadfence() (gpu scope) emits CCTL.IVALL on
// sm_103a -> invalidates this SM's L1D at every arrival, making plain cached
// loads of cross-phase data safe after the barrier releases.
__device__ __forceinline__ void bar_mono(int* ctr, int target) {
    __syncthreads();
    if (threadIdx.x == 0) {
        __threadfence();
        atomicAdd(ctr, 1);
        while (*(volatile int*)ctr < target) { __nanosleep(64); }
    }
    __syncthreads();
}

// ---------------- k_init: W split + counter/barrier reset -----------------
__global__ void k_init(const float* __restrict__ W) {
    int i = blockIdx.x * 256 + threadIdx.x;
    if (i < HID * F_INN) {
        float w = W[i];
        uint32_t b = __float_as_uint(w);
        float h = __uint_as_float(b & 0xFFFF0000u);
        g_whi[i] = (uint16_t)(b >> 16);
        __nv_bfloat16 lo = __float2bfloat16(w - h);
        g_wlo[i] = *reinterpret_cast<uint16_t*>(&lo);
    }
    if (i < N_NODES) { g_cnt[i] = 0; g_deg[i] = 0; }
    if (i < 4) g_bars[i] = 0;
}

// ================= persistent CSR kernel (one launch) ======================
__global__ __launch_bounds__(256, 2)
void k_csr(const int* __restrict__ row, const int* __restrict__ col) {
    __shared__ int s[256];
    int tid = threadIdx.x;
    int gtid = blockIdx.x * 256 + tid;
    const int NT = CGRID * 256;

    for (int e = gtid; e < N_EDGES; e += NT) {
        atomicAdd(&g_deg[row[e]], 1);
        atomicAdd(&g_cnt[col[e]], 1);
    }
    bar_mono(&g_bars[0], 1 * CGRID);

    {
        int i = gtid;
        int v = (i < N_NODES) ? g_cnt[i] : 0;
        s[tid] = v;
        __syncthreads();
        #pragma unroll
        for (int off = 1; off < 256; off <<= 1) {
            int t = (tid >= off) ? s[tid - off] : 0;
            __syncthreads();
            s[tid] += t;
            __syncthreads();
        }
        if (i < N_NODES) g_indptr[i] = s[tid] - v;
        if (tid == 255) g_bsum[blockIdx.x] = s[255];
    }
    bar_mono(&g_bars[0], 2 * CGRID);

    if (blockIdx.x == 0) {
        int v = (tid < CGRID) ? g_bsum[tid] : 0;
        s[tid] = v;
        __syncthreads();
        #pragma unroll
        for (int off = 1; off < 256; off <<= 1) {
            int t = (tid >= off) ? s[tid - off] : 0;
            __syncthreads();
            s[tid] += t;
            __syncthreads();
        }
        g_boff[tid] = s[tid] - v;
        if (tid == 0) g_indptr[N_NODES] = N_EDGES;
    }
    bar_mono(&g_bars[0], 3 * CGRID);

    for (int i = gtid; i < N_NODES; i += NT) {
        int ip = g_indptr[i] + g_boff[i >> 8];
        g_indptr[i] = ip;
        g_cursor[i] = ip;
        int d = g_deg[i];
        g_nd[i] = rsqrtf((float)(d < 1 ? 1 : d));
    }
    bar_mono(&g_bars[0], 4 * CGRID);

    for (int e = gtid; e < N_EDGES; e += NT) {
        int r = row[e], c = col[e];
        int pos = atomicAdd(&g_cursor[c], 1);
        g_esrc[pos] = r;
        g_ew[pos] = g_nd[r] * g_nd[c];
    }
}

// ============ GEMM1 (proven): 64x128, cp.async W, fused layer0 pq ==========
#define TSTRIDE 40
#define SM_AS(buf)   ((buf) * 10240)
#define SM_WS(buf)   (20480 + (buf) * 20480)
#define SM_BIAS      61440
#define GEMM_SMEM    61952

__global__ __launch_bounds__(256, 2)
void k_gemm1_mma(const float* __restrict__ A, const float* __restrict__ bias,
                 const float* __restrict__ gw0,
                 __half* __restrict__ h, float* __restrict__ raw,
                 float* __restrict__ p0, float* __restrict__ q0, int n) {
    extern __shared__ char smem[];
    uint32_t sb = smem_u32(smem);
    float* sbias = (float*)(smem + SM_BIAS);
    __shared__ float sp[64], sq[64];

    int tid = threadIdx.x;
    int wid = tid >> 5, lane = tid & 31;
    int wm = (wid >> 2) * 32;
    int wn = (wid & 3) * 32;
    int blockM = blockIdx.x * 64;

    if (tid < HID) sbias[tid] = bias[tid];
    if (tid < 64) { sp[tid] = 0.f; sq[tid] = 0.f; }

    float acc[2][4][4];
    #pragma unroll
    for (int i = 0; i < 2; i++)
        #pragma unroll
        for (int j = 0; j < 4; j++)
            #pragma unroll
            for (int k = 0; k < 4; k++) acc[i][j][k] = 0.f;

    int lr  = tid >> 3;
    int lc4 = (tid & 7) * 4;
    int a_row = lane & 15, a_kh = (lane >> 4) * 8;
    int b_row = lane & 7,  b_kh = ((lane >> 3) & 1) * 8;

    float4 aReg[2];

    #pragma unroll
    for (int it = 0; it < 2; it++) {
        int gr = blockM + lr + it * 32;
        aReg[it] = (gr < n) ? *(const float4*)&A[(size_t)gr * F_INN + lc4]
                            : make_float4(0.f, 0.f, 0.f, 0.f);
    }
    #pragma unroll
    for (int it = 0; it < 2; it++) {
        int row = lr + it * 32;
        int boff = SM_AS(0) + (row * TSTRIDE + lc4) * 2;
        float4 av = aReg[it];
        uint32_t bx = __float_as_uint(av.x), by = __float_as_uint(av.y);
        uint32_t bz = __float_as_uint(av.z), bw = __float_as_uint(av.w);
        *(uint2*)(smem + boff) = make_uint2(__byte_perm(bx, by, 0x7632),
                                            __byte_perm(bz, bw, 0x7632));
        float lx = av.x - __uint_as_float(bx & 0xFFFF0000u);
        float ly = av.y - __uint_as_float(by & 0xFFFF0000u);
        float lz = av.z - __uint_as_float(bz & 0xFFFF0000u);
        float lw = av.w - __uint_as_float(bw & 0xFFFF0000u);
        *(uint2*)(smem + boff + 5120) = make_uint2(pack_bf16lo(lx, ly), pack_bf16lo(lz, lw));
    }
    #pragma unroll
    for (int it = 0; it < 2; it++) {
        int idx = tid + it * 256;
        int row = idx >> 2, seg = idx & 3;
        uint32_t dst = sb + SM_WS(0) + (row * TSTRIDE + seg * 8) * 2;
        cp_async16(dst,         &g_whi[row * F_INN + 0 + seg * 8]);
        cp_async16(dst + 10240, &g_wlo[row * F_INN + 0 + seg * 8]);
    }
    CP_COMMIT();
    #pragma unroll
    for (int it = 0; it < 2; it++) {
        int gr = blockM + lr + it * 32;
        aReg[it] = (gr < n) ? *(const float4*)&A[(size_t)gr * F_INN + 32 + lc4]
                            : make_float4(0.f, 0.f, 0.f, 0.f);
    }
    #pragma unroll
    for (int it = 0; it < 2; it++) {
        int idx = tid + it * 256;
        int row = idx >> 2, seg = idx & 3;
        uint32_t dst = sb + SM_WS(1) + (row * TSTRIDE + seg * 8) * 2;
        cp_async16(dst,         &g_whi[row * F_INN + 32 + seg * 8]);
        cp_async16(dst + 10240, &g_wlo[row * F_INN + 32 + seg * 8]);
    }
    CP_COMMIT();
    CP_WAIT(1);
    __syncthreads();

    for (int ch = 0; ch < 16; ch++) {
        int cur = ch & 1;
        uint32_t aBase = sb + SM_AS(cur);
        uint32_t wBase = sb + SM_WS(cur);

        if (ch + 1 < 16) {
            #pragma unroll
            for (int it = 0; it < 2; it++) {
                int row = lr + it * 32;
                int boff = SM_AS(cur ^ 1) + (row * TSTRIDE + lc4) * 2;
                float4 av = aReg[it];
                uint32_t bx = __float_as_uint(av.x), by = __float_as_uint(av.y);
                uint32_t bz = __float_as_uint(av.z), bw = __float_as_uint(av.w);
                *(uint2*)(smem + boff) = make_uint2(__byte_perm(bx, by, 0x7632),
                                                    __byte_perm(bz, bw, 0x7632));
                float lx = av.x - __uint_as_float(bx & 0xFFFF0000u);
                float ly = av.y - __uint_as_float(by & 0xFFFF0000u);
                float lz = av.z - __uint_as_float(bz & 0xFFFF0000u);
                float lw = av.w - __uint_as_float(bw & 0xFFFF0000u);
                *(uint2*)(smem + boff + 5120) = make_uint2(pack_bf16lo(lx, ly), pack_bf16lo(lz, lw));
            }
            if (ch + 2 < 16) {
                int k0n = (ch + 2) * 32;
                #pragma unroll
                for (int it = 0; it < 2; it++) {
                    int gr = blockM + lr + it * 32;
                    aReg[it] = (gr < n) ? *(const float4*)&A[(size_t)gr * F_INN + k0n + lc4]
                                        : make_float4(0.f, 0.f, 0.f, 0.f);
                }
            }
        }

        #pragma unroll
        for (int kk = 0; kk < 32; kk += 16) {
            uint32_t ah[2][4], al[2][4];
            #pragma unroll
            for (int mt = 0; mt < 2; mt++) {
                uint32_t ao = aBase + ((wm + mt * 16 + a_row) * TSTRIDE + kk + a_kh) * 2;
                ldsm_x4(ah[mt], ao);
                ldsm_x4(al[mt], ao + 5120);
            }
            uint32_t bh[4][2], bl[4][2];
            #pragma unroll
            for (int nt = 0; nt < 4; nt++) {
                uint32_t bo = wBase + ((wn + nt * 8 + b_row) * TSTRIDE + kk + b_kh) * 2;
                ldsm_x2(bh[nt], bo);
                ldsm_x2(bl[nt], bo + 10240);
            }
            #pragma unroll
            for (int mt = 0; mt < 2; mt++)
                #pragma unroll
                for (int nt = 0; nt < 4; nt++) {
                    mma_bf16(acc[mt][nt], ah[mt], bh[nt]);
                    mma_bf16(acc[mt][nt], ah[mt], bl[nt]);
                    mma_bf16(acc[mt][nt], al[mt], bh[nt]);
                }
        }
        __syncthreads();

        if (ch + 2 < 16) {
            int k0n = (ch + 2) * 32;
            #pragma unroll
            for (int it = 0; it < 2; it++) {
                int idx = tid + it * 256;
                int row = idx >> 2, seg = idx & 3;
                uint32_t dst = sb + SM_WS(cur) + (row * TSTRIDE + seg * 8) * 2;
                cp_async16(dst,         &g_whi[row * F_INN + k0n + seg * 8]);
                cp_async16(dst + 10240, &g_wlo[row * F_INN + k0n + seg * 8]);
            }
            CP_COMMIT();
            CP_WAIT(1);
        } else {
            CP_WAIT(0);
        }
    }

    #pragma unroll
    for (int mt = 0; mt < 2; mt++) {
        int lm0 = wm + mt * 16 + (lane >> 2);
        int lm1 = lm0 + 8;
        int m0 = blockM + lm0, m1 = blockM + lm1;
        float pa0 = 0.f, qa0 = 0.f, pa1 = 0.f, qa1 = 0.f;
        #pragma unroll
        for (int nt = 0; nt < 4; nt++) {
            int n0 = wn + nt * 8 + 2 * (lane & 3);
            float b0 = sbias[n0], b1 = sbias[n0 + 1];
            float w10 = __ldg(&gw0[n0]),       w11 = __ldg(&gw0[n0 + 1]);
            float w20 = __ldg(&gw0[HID + n0]), w21 = __ldg(&gw0[HID + n0 + 1]);
            if (m0 < n) {
                float vx = fmaxf(acc[mt][nt][0] + b0, 0.f);
                float vy = fmaxf(acc[mt][nt][1] + b1, 0.f);
                *(float2*)&raw[(size_t)m0 * HID + n0] = make_float2(vx, vy);
                *(__half2*)&h[(size_t)m0 * HID + n0] = __floats2half2_rn(vx, vy);
                pa0 += vx * w10 + vy * w11;
                qa0 += vx * w20 + vy * w21;
            }
            if (m1 < n) {
                float vx = fmaxf(acc[mt][nt][2] + b0, 0.f);
                float vy = fmaxf(acc[mt][nt][3] + b1, 0.f);
                *(float2*)&raw[(size_t)m1 * HID + n0] = make_float2(vx, vy);
                *(__half2*)&h[(size_t)m1 * HID + n0] = __floats2half2_rn(vx, vy);
                pa1 += vx * w10 + vy * w11;
                qa1 += vx * w20 + vy * w21;
            }
        }
        atomicAdd(&sp[lm0], pa0); atomicAdd(&sq[lm0], qa0);
        atomicAdd(&sp[lm1], pa1); atomicAdd(&sq[lm1], qa1);
    }
    __syncthreads();
    if (tid < 64 && blockM + tid < n) {
        p0[blockM + tid] = sp[tid];
        q0[blockM + tid] = sq[tid];
    }
}

// ---------------- agg layer body (plain cached loads; barrier invalidates L1)
__device__ __forceinline__ void agg_layer4(const __half* __restrict__ h,
                                           __half* __restrict__ hn, float gb,
                                           const float* __restrict__ p_in,
                                           const float* __restrict__ q_in,
                                           float* __restrict__ p_out,
                                           float* __restrict__ q_out,
                                           const float* __restrict__ gw_next) {
    int gwarp = blockIdx.x * 8 + (threadIdx.x >> 5);
    int lane = threadIdx.x & 31;
    const uint2* h2 = (const uint2*)h;

    for (int node = gwarp; node < N_NODES; node += AWARPS) {
        int beg = g_indptr[node], end = g_indptr[node + 1];
        float qc = q_in[node];
        float4 r = ((const float4*)g_raw)[node * 32 + lane];
        float4 acc = make_float4(EPS_V * r.x, EPS_V * r.y, EPS_V * r.z, EPS_V * r.w);

        for (int e = beg; e < end; e += 32) {
            int idx = e + lane;
            int src = 0; float nrm = 0.f;
            if (idx < end) {
                src = g_esrc[idx];
                nrm = tanhf(p_in[src] + qc + gb) * g_ew[idx];
            }
            int m = end - e; if (m > 32) m = 32;
            int j = 0;
            for (; j + 4 <= m; j += 4) {
                int s0 = __shfl_sync(0xffffffffu, src, j + 0);
                int s1 = __shfl_sync(0xffffffffu, src, j + 1);
                int s2 = __shfl_sync(0xffffffffu, src, j + 2);
                int s3 = __shfl_sync(0xffffffffu, src, j + 3);
                float n0 = __shfl_sync(0xffffffffu, nrm, j + 0);
                float n1 = __shfl_sync(0xffffffffu, nrm, j + 1);
                float n2 = __shfl_sync(0xffffffffu, nrm, j + 2);
                float n3 = __shfl_sync(0xffffffffu, nrm, j + 3);
                uint2 v0 = h2[(size_t)s0 * 32 + lane];
                uint2 v1 = h2[(size_t)s1 * 32 + lane];
                uint2 v2 = h2[(size_t)s2 * 32 + lane];
                uint2 v3 = h2[(size_t)s3 * 32 + lane];
                float2 a0 = __half22float2(*(__half2*)&v0.x), c0 = __half22float2(*(__half2*)&v0.y);
                float2 a1 = __half22float2(*(__half2*)&v1.x), c1 = __half22float2(*(__half2*)&v1.y);
                float2 a2 = __half22float2(*(__half2*)&v2.x), c2 = __half22float2(*(__half2*)&v2.y);
                float2 a3 = __half22float2(*(__half2*)&v3.x), c3 = __half22float2(*(__half2*)&v3.y);
                acc.x = fmaf(n0, a0.x, acc.x); acc.y = fmaf(n0, a0.y, acc.y);
                acc.z = fmaf(n0, c0.x, acc.z); acc.w = fmaf(n0, c0.y, acc.w);
                acc.x = fmaf(n1, a1.x, acc.x); acc.y = fmaf(n1, a1.y, acc.y);
                acc.z = fmaf(n1, c1.x, acc.z); acc.w = fmaf(n1, c1.y, acc.w);
                acc.x = fmaf(n2, a2.x, acc.x); acc.y = fmaf(n2, a2.y, acc.y);
                acc.z = fmaf(n2, c2.x, acc.z); acc.w = fmaf(n2, c2.y, acc.w);
                acc.x = fmaf(n3, a3.x, acc.x); acc.y = fmaf(n3, a3.y, acc.y);
                acc.z = fmaf(n3, c3.x, acc.z); acc.w = fmaf(n3, c3.y, acc.w);
            }
            for (; j < m; j++) {
                int   s  = __shfl_sync(0xffffffffu, src, j);
                float nm = __shfl_sync(0xffffffffu, nrm, j);
                uint2 hv = h2[(size_t)s * 32 + lane];
                float2 f01 = __half22float2(*(__half2*)&hv.x);
                float2 f23 = __half22float2(*(__half2*)&hv.y);
                acc.x = fmaf(nm, f01.x, acc.x);
                acc.y = fmaf(nm, f01.y, acc.y);
                acc.z = fmaf(nm, f23.x, acc.z);
                acc.w = fmaf(nm, f23.y, acc.w);
            }
        }
        uint2 packed;
        *(__half2*)&packed.x = __floats2half2_rn(acc.x, acc.y);
        *(__half2*)&packed.y = __floats2half2_rn(acc.z, acc.w);
        ((uint2*)hn)[node * 32 + lane] = packed;

        if (gw_next) {
            float4 w1 = ((const float4*)gw_next)[lane];
            float4 w2 = ((const float4*)gw_next)[32 + lane];
            float a = acc.x * w1.x + acc.y * w1.y + acc.z * w1.z + acc.w * w1.w;
            float b = acc.x * w2.x + acc.y * w2.y + acc.z * w2.z + acc.w * w2.w;
            #pragma unroll
            for (int o = 16; o > 0; o >>= 1) {
                a += __shfl_down_sync(0xffffffffu, a, o);
                b += __shfl_down_sync(0xffffffffu, b, o);
            }
            if (lane == 0) { p_out[node] = a; q_out[node] = b; }
        }
    }
}

// ========== persistent 4-layer propagation + classifier kernel =============
__global__ __launch_bounds__(256, 6)
void k_agg4(const float* __restrict__ gb, const float* __restrict__ gw,
            const float* __restrict__ t2w, const float* __restrict__ t2b,
            float* __restrict__ out) {
    __shared__ float ws[N_CLS * HID];       // 20 KB
    __shared__ float hs[6 * HID];           // 3 KB
    __shared__ float logits[6 * N_CLS];     // ~1 KB

    int tid = threadIdx.x;

    float gb0 = __ldg(&gb[0]), gb1 = __ldg(&gb[1]);
    float gb2 = __ldg(&gb[2]), gb3 = __ldg(&gb[3]);
    agg_layer4(g_hA, g_hB, gb0, g_pA, g_qA, g_pB, g_qB, gw + 1 * 2 * HID);
    bar_mono(&g_bars[1], 1 * AGRID);
    agg_layer4(g_hB, g_hA, gb1, g_pB, g_qB, g_pA, g_qA, gw + 2 * 2 * HID);
    bar_mono(&g_bars[1], 2 * AGRID);
    agg_layer4(g_hA, g_hB, gb2, g_pA, g_qA, g_pB, g_qB, gw + 3 * 2 * HID);
    bar_mono(&g_bars[1], 3 * AGRID);
    agg_layer4(g_hB, g_hA, gb3, g_pB, g_qB, (float*)0, (float*)0, (const float*)0);
    bar_mono(&g_bars[1], 4 * AGRID);

    // classifier + log_softmax over final h (g_hA), 6 nodes per block-iter
    for (int i = tid; i < N_CLS * HID; i += 256) ws[i] = t2w[i];
    __syncthreads();

    int ln = tid / N_CLS;      // 0..5 for tid<240
    int c  = tid % N_CLS;
    for (int nb = blockIdx.x * 6; nb < N_NODES; nb += AGRID * 6) {
        for (int i = tid; i < 6 * HID; i += 256) {
            int nn = nb + i / HID;
            hs[i] = (nn < N_NODES) ? __half2float(g_hA[(size_t)nn * HID + (i % HID)]) : 0.f;
        }
        __syncthreads();
        if (tid < 240) {
            float accv = __ldg(&t2b[c]);
            const float4* hp = (const float4*)&hs[ln * HID];
            const float4* wp = (const float4*)&ws[c * HID];
            #pragma unroll
            for (int k = 0; k < HID / 4; k++) {
                float4 hv = hp[k], wv = wp[k];
                accv = fmaf(hv.x, wv.x, accv);
                accv = fmaf(hv.y, wv.y, accv);
                accv = fmaf(hv.z, wv.z, accv);
                accv = fmaf(hv.w, wv.w, accv);
            }
            logits[ln * N_CLS + c] = accv;
        }
        __syncthreads();
        if (tid < 240) {
            float mx = -1e30f;
            #pragma unroll 8
            for (int j = 0; j < N_CLS; j++) mx = fmaxf(mx, logits[ln * N_CLS + j]);
            float sum = 0.f;
            #pragma unroll 8
            for (int j = 0; j < N_CLS; j++) sum += expf(logits[ln * N_CLS + j] - mx);
            int nn = nb + ln;
            if (nn < N_NODES)
                out[(size_t)nn * N_CLS + c] = logits[ln * N_CLS + c] - mx - logf(sum);
        }
        __syncthreads();
    }
}

// ---------------- host launcher: fork/join + persistent kernels -----------
extern "C" void kernel_launch(void* const* d_in, const int* in_sizes, int n_in,
                              void* d_out, int out_size) {
    const float* x   = (const float*)d_in[0];
    const int*   ei  = (const int*)d_in[1];
    const float* t1w = (const float*)d_in[2];
    const float* t1b = (const float*)d_in[3];
    const float* gw  = (const float*)d_in[4];
    const float* gb  = (const float*)d_in[5];
    const float* t2w = (const float*)d_in[6];
    const float* t2b = (const float*)d_in[7];
    float* out = (float*)d_out;

    const int* row = ei;
    const int* col = ei + N_EDGES;

    __half *hA;
    float *raw, *pA, *qA;
    cudaGetSymbolAddress((void**)&hA,  g_hA);
    cudaGetSymbolAddress((void**)&raw, g_raw);
    cudaGetSymbolAddress((void**)&pA,  g_pA);
    cudaGetSymbolAddress((void**)&qA,  g_qA);

    static cudaStream_t s_side = 0;
    static cudaEvent_t  e_fork = 0, e_join = 0;
    static bool inited = false;
    if (!inited) {
        cudaStreamCreateWithFlags(&s_side, cudaStreamNonBlocking);
        cudaEventCreateWithFlags(&e_fork, cudaEventDisableTiming);
        cudaEventCreateWithFlags(&e_join, cudaEventDisableTiming);
        cudaFuncSetAttribute(k_gemm1_mma, cudaFuncAttributeMaxDynamicSharedMemorySize, GEMM_SMEM);
        inited = true;
    }

    k_init<<<(HID * F_INN + 255) / 256, 256>>>(t1w);
    cudaEventRecord(e_fork, 0);
    cudaStreamWaitEvent(s_side, e_fork, 0);

    k_csr<<<CGRID, 256, 0, s_side>>>(row, col);
    cudaEventRecord(e_join, s_side);

    k_gemm1_mma<<<(N_NODES + 63) / 64, 256, GEMM_SMEM>>>(x, t1b, gw, hA, raw, pA, qA, N_NODES);

    cudaStreamWaitEvent(0, e_join, 0);
    k_agg4<<<AGRID, 256>>>(gb, gw, t2w, t2b, out);
}

// round 14
// speedup vs baseline: 1.0649x; 1.0649x over previous
#include <cuda_runtime.h>
#include <cuda_bf16.h>
#include <cuda_fp16.h>
#include <math.h>
#include <stdint.h>

#define N_NODES 50000
#define N_EDGES 800000
#define F_INN   512
#define HID     128
#define N_CLS   40
#define EPS_V   0.3f

#define CGRID   196

// ---------------- scratch (static device globals; no allocations) ----------
__device__ float  g_raw[N_NODES * HID];
__device__ __half g_hA [N_NODES * HID];
__device__ __half g_hB [N_NODES * HID];
__device__ float  g_pA [N_NODES];
__device__ float  g_qA [N_NODES];
__device__ float  g_pB [N_NODES];
__device__ float  g_qB [N_NODES];
__device__ float  g_nd [N_NODES];
__device__ float  g_ew [N_EDGES];
__device__ int    g_esrc[N_EDGES];
__device__ int    g_indptr[N_NODES + 1];
__device__ int    g_cnt[N_NODES];
__device__ int    g_deg[N_NODES];
__device__ int    g_cursor[N_NODES];
__device__ int    g_bsum[256];
__device__ int    g_boff[256];
__device__ int    g_bars[4];
__device__ uint16_t g_whi[HID * F_INN];
__device__ uint16_t g_wlo[HID * F_INN];

// ================= PTX helpers (baseline sm_80+ PTX only) =================
__device__ __forceinline__ uint32_t smem_u32(const void* p) {
    uint32_t a;
    asm("{ .reg .u64 t; cvta.to.shared.u64 t, %1; cvt.u32.u64 %0, t; }" : "=r"(a) : "l"(p));
    return a;
}
__device__ __forceinline__ void ldsm_x4(uint32_t (&r)[4], uint32_t addr) {
    asm volatile("ldmatrix.sync.aligned.m8n8.x4.shared.b16 {%0,%1,%2,%3}, [%4];"
        : "=r"(r[0]), "=r"(r[1]), "=r"(r[2]), "=r"(r[3]) : "r"(addr));
}
__device__ __forceinline__ void ldsm_x2(uint32_t (&r)[2], uint32_t addr) {
    asm volatile("ldmatrix.sync.aligned.m8n8.x2.shared.b16 {%0,%1}, [%2];"
        : "=r"(r[0]), "=r"(r[1]) : "r"(addr));
}
__device__ __forceinline__ void mma_bf16(float (&d)[4], const uint32_t (&a)[4], const uint32_t (&b)[2]) {
    asm volatile("mma.sync.aligned.m16n8k16.row.col.f32.bf16.bf16.f32 "
        "{%0,%1,%2,%3}, {%4,%5,%6,%7}, {%8,%9}, {%0,%1,%2,%3};"
        : "+f"(d[0]), "+f"(d[1]), "+f"(d[2]), "+f"(d[3])
        : "r"(a[0]), "r"(a[1]), "r"(a[2]), "r"(a[3]), "r"(b[0]), "r"(b[1]));
}
__device__ __forceinline__ void cp_async16(uint32_t saddr, const void* gaddr) {
    asm volatile("cp.async.cg.shared.global [%0], [%1], 16;" :: "r"(saddr), "l"(gaddr));
}
#define CP_COMMIT() asm volatile("cp.async.commit_group;" ::: "memory")
#define CP_WAIT(N)  asm volatile("cp.async.wait_group %0;" :: "n"(N) : "memory")

__device__ __forceinline__ uint32_t pack_bf16lo(float x, float y) {
    __nv_bfloat162 t = __floats2bfloat162_rn(x, y);
    return *reinterpret_cast<uint32_t*>(&t);
}

// monotonic grid barrier (k_csr only)
__device__ __forceinline__ void bar_mono(int* ctr, int target) {
    __syncthreads();
    if (threadIdx.x == 0) {
        __threadfence();
        atomicAdd(ctr, 1);
        while (*(volatile int*)ctr < target) { __nanosleep(64); }
    }
    __syncthreads();
}

// ---------------- k_init: W split + counter/barrier reset -----------------
__global__ void k_init(const float* __restrict__ W) {
    int i = blockIdx.x * 256 + threadIdx.x;
    if (i < HID * F_INN) {
        float w = W[i];
        uint32_t b = __float_as_uint(w);
        float h = __uint_as_float(b & 0xFFFF0000u);
        g_whi[i] = (uint16_t)(b >> 16);
        __nv_bfloat16 lo = __float2bfloat16(w - h);
        g_wlo[i] = *reinterpret_cast<uint16_t*>(&lo);
    }
    if (i < N_NODES) { g_cnt[i] = 0; g_deg[i] = 0; }
    if (i < 4) g_bars[i] = 0;
}

// ================= persistent CSR kernel (one launch; proven in R12) =======
__global__ __launch_bounds__(256, 2)
void k_csr(const int* __restrict__ row, const int* __restrict__ col) {
    __shared__ int s[256];
    int tid = threadIdx.x;
    int gtid = blockIdx.x * 256 + tid;
    const int NT = CGRID * 256;

    for (int e = gtid; e < N_EDGES; e += NT) {
        atomicAdd(&g_deg[row[e]], 1);
        atomicAdd(&g_cnt[col[e]], 1);
    }
    bar_mono(&g_bars[0], 1 * CGRID);

    {
        int i = gtid;
        int v = (i < N_NODES) ? g_cnt[i] : 0;
        s[tid] = v;
        __syncthreads();
        #pragma unroll
        for (int off = 1; off < 256; off <<= 1) {
            int t = (tid >= off) ? s[tid - off] : 0;
            __syncthreads();
            s[tid] += t;
            __syncthreads();
        }
        if (i < N_NODES) g_indptr[i] = s[tid] - v;
        if (tid == 255) g_bsum[blockIdx.x] = s[255];
    }
    bar_mono(&g_bars[0], 2 * CGRID);

    if (blockIdx.x == 0) {
        int v = (tid < CGRID) ? g_bsum[tid] : 0;
        s[tid] = v;
        __syncthreads();
        #pragma unroll
        for (int off = 1; off < 256; off <<= 1) {
            int t = (tid >= off) ? s[tid - off] : 0;
            __syncthreads();
            s[tid] += t;
            __syncthreads();
        }
        g_boff[tid] = s[tid] - v;
        if (tid == 0) g_indptr[N_NODES] = N_EDGES;
    }
    bar_mono(&g_bars[0], 3 * CGRID);

    for (int i = gtid; i < N_NODES; i += NT) {
        int ip = g_indptr[i] + g_boff[i >> 8];
        g_indptr[i] = ip;
        g_cursor[i] = ip;
        int d = g_deg[i];
        g_nd[i] = rsqrtf((float)(d < 1 ? 1 : d));
    }
    bar_mono(&g_bars[0], 4 * CGRID);

    for (int e = gtid; e < N_EDGES; e += NT) {
        int r = row[e], c = col[e];
        int pos = atomicAdd(&g_cursor[c], 1);
        g_esrc[pos] = r;
        g_ew[pos] = g_nd[r] * g_nd[c];
    }
}

// ============ GEMM1 (proven 88us): 64x128, cp.async W, fused L0 pq =========
#define TSTRIDE 40
#define SM_AS(buf)   ((buf) * 10240)
#define SM_WS(buf)   (20480 + (buf) * 20480)
#define SM_BIAS      61440
#define GEMM_SMEM    61952

__global__ __launch_bounds__(256, 2)
void k_gemm1_mma(const float* __restrict__ A, const float* __restrict__ bias,
                 const float* __restrict__ gw0,
                 __half* __restrict__ h, float* __restrict__ raw,
                 float* __restrict__ p0, float* __restrict__ q0, int n) {
    extern __shared__ char smem[];
    uint32_t sb = smem_u32(smem);
    float* sbias = (float*)(smem + SM_BIAS);
    __shared__ float sp[64], sq[64];

    int tid = threadIdx.x;
    int wid = tid >> 5, lane = tid & 31;
    int wm = (wid >> 2) * 32;
    int wn = (wid & 3) * 32;
    int blockM = blockIdx.x * 64;

    if (tid < HID) sbias[tid] = bias[tid];
    if (tid < 64) { sp[tid] = 0.f; sq[tid] = 0.f; }

    float acc[2][4][4];
    #pragma unroll
    for (int i = 0; i < 2; i++)
        #pragma unroll
        for (int j = 0; j < 4; j++)
            #pragma unroll
            for (int k = 0; k < 4; k++) acc[i][j][k] = 0.f;

    int lr  = tid >> 3;
    int lc4 = (tid & 7) * 4;
    int a_row = lane & 15, a_kh = (lane >> 4) * 8;
    int b_row = lane & 7,  b_kh = ((lane >> 3) & 1) * 8;

    float4 aReg[2];

    #pragma unroll
    for (int it = 0; it < 2; it++) {
        int gr = blockM + lr + it * 32;
        aReg[it] = (gr < n) ? *(const float4*)&A[(size_t)gr * F_INN + lc4]
                            : make_float4(0.f, 0.f, 0.f, 0.f);
    }
    #pragma unroll
    for (int it = 0; it < 2; it++) {
        int row = lr + it * 32;
        int boff = SM_AS(0) + (row * TSTRIDE + lc4) * 2;
        float4 av = aReg[it];
        uint32_t bx = __float_as_uint(av.x), by = __float_as_uint(av.y);
        uint32_t bz = __float_as_uint(av.z), bw = __float_as_uint(av.w);
        *(uint2*)(smem + boff) = make_uint2(__byte_perm(bx, by, 0x7632),
                                            __byte_perm(bz, bw, 0x7632));
        float lx = av.x - __uint_as_float(bx & 0xFFFF0000u);
        float ly = av.y - __uint_as_float(by & 0xFFFF0000u);
        float lz = av.z - __uint_as_float(bz & 0xFFFF0000u);
        float lw = av.w - __uint_as_float(bw & 0xFFFF0000u);
        *(uint2*)(smem + boff + 5120) = make_uint2(pack_bf16lo(lx, ly), pack_bf16lo(lz, lw));
    }
    #pragma unroll
    for (int it = 0; it < 2; it++) {
        int idx = tid + it * 256;
        int row = idx >> 2, seg = idx & 3;
        uint32_t dst = sb + SM_WS(0) + (row * TSTRIDE + seg * 8) * 2;
        cp_async16(dst,         &g_whi[row * F_INN + 0 + seg * 8]);
        cp_async16(dst + 10240, &g_wlo[row * F_INN + 0 + seg * 8]);
    }
    CP_COMMIT();
    #pragma unroll
    for (int it = 0; it < 2; it++) {
        int gr = blockM + lr + it * 32;
        aReg[it] = (gr < n) ? *(const float4*)&A[(size_t)gr * F_INN + 32 + lc4]
                            : make_float4(0.f, 0.f, 0.f, 0.f);
    }
    #pragma unroll
    for (int it = 0; it < 2; it++) {
        int idx = tid + it * 256;
        int row = idx >> 2, seg = idx & 3;
        uint32_t dst = sb + SM_WS(1) + (row * TSTRIDE + seg * 8) * 2;
        cp_async16(dst,         &g_whi[row * F_INN + 32 + seg * 8]);
        cp_async16(dst + 10240, &g_wlo[row * F_INN + 32 + seg * 8]);
    }
    CP_COMMIT();
    CP_WAIT(1);
    __syncthreads();

    for (int ch = 0; ch < 16; ch++) {
        int cur = ch & 1;
        uint32_t aBase = sb + SM_AS(cur);
        uint32_t wBase = sb + SM_WS(cur);

        if (ch + 1 < 16) {
            #pragma unroll
            for (int it = 0; it < 2; it++) {
                int row = lr + it * 32;
                int boff = SM_AS(cur ^ 1) + (row * TSTRIDE + lc4) * 2;
                float4 av = aReg[it];
                uint32_t bx = __float_as_uint(av.x), by = __float_as_uint(av.y);
                uint32_t bz = __float_as_uint(av.z), bw = __float_as_uint(av.w);
                *(uint2*)(smem + boff) = make_uint2(__byte_perm(bx, by, 0x7632),
                                                    __byte_perm(bz, bw, 0x7632));
                float lx = av.x - __uint_as_float(bx & 0xFFFF0000u);
                float ly = av.y - __uint_as_float(by & 0xFFFF0000u);
                float lz = av.z - __uint_as_float(bz & 0xFFFF0000u);
                float lw = av.w - __uint_as_float(bw & 0xFFFF0000u);
                *(uint2*)(smem + boff + 5120) = make_uint2(pack_bf16lo(lx, ly), pack_bf16lo(lz, lw));
            }
            if (ch + 2 < 16) {
                int k0n = (ch + 2) * 32;
                #pragma unroll
                for (int it = 0; it < 2; it++) {
                    int gr = blockM + lr + it * 32;
                    aReg[it] = (gr < n) ? *(const float4*)&A[(size_t)gr * F_INN + k0n + lc4]
                                        : make_float4(0.f, 0.f, 0.f, 0.f);
                }
            }
        }

        #pragma unroll
        for (int kk = 0; kk < 32; kk += 16) {
            uint32_t ah[2][4], al[2][4];
            #pragma unroll
            for (int mt = 0; mt < 2; mt++) {
                uint32_t ao = aBase + ((wm + mt * 16 + a_row) * TSTRIDE + kk + a_kh) * 2;
                ldsm_x4(ah[mt], ao);
                ldsm_x4(al[mt], ao + 5120);
            }
            uint32_t bh[4][2], bl[4][2];
            #pragma unroll
            for (int nt = 0; nt < 4; nt++) {
                uint32_t bo = wBase + ((wn + nt * 8 + b_row) * TSTRIDE + kk + b_kh) * 2;
                ldsm_x2(bh[nt], bo);
                ldsm_x2(bl[nt], bo + 10240);
            }
            #pragma unroll
            for (int mt = 0; mt < 2; mt++)
                #pragma unroll
                for (int nt = 0; nt < 4; nt++) {
                    mma_bf16(acc[mt][nt], ah[mt], bh[nt]);
                    mma_bf16(acc[mt][nt], ah[mt], bl[nt]);
                    mma_bf16(acc[mt][nt], al[mt], bh[nt]);
                }
        }
        __syncthreads();

        if (ch + 2 < 16) {
            int k0n = (ch + 2) * 32;
            #pragma unroll
            for (int it = 0; it < 2; it++) {
                int idx = tid + it * 256;
                int row = idx >> 2, seg = idx & 3;
                uint32_t dst = sb + SM_WS(cur) + (row * TSTRIDE + seg * 8) * 2;
                cp_async16(dst,         &g_whi[row * F_INN + k0n + seg * 8]);
                cp_async16(dst + 10240, &g_wlo[row * F_INN + k0n + seg * 8]);
            }
            CP_COMMIT();
            CP_WAIT(1);
        } else {
            CP_WAIT(0);
        }
    }

    #pragma unroll
    for (int mt = 0; mt < 2; mt++) {
        int lm0 = wm + mt * 16 + (lane >> 2);
        int lm1 = lm0 + 8;
        int m0 = blockM + lm0, m1 = blockM + lm1;
        float pa0 = 0.f, qa0 = 0.f, pa1 = 0.f, qa1 = 0.f;
        #pragma unroll
        for (int nt = 0; nt < 4; nt++) {
            int n0 = wn + nt * 8 + 2 * (lane & 3);
            float b0 = sbias[n0], b1 = sbias[n0 + 1];
            float w10 = __ldg(&gw0[n0]),       w11 = __ldg(&gw0[n0 + 1]);
            float w20 = __ldg(&gw0[HID + n0]), w21 = __ldg(&gw0[HID + n0 + 1]);
            if (m0 < n) {
                float vx = fmaxf(acc[mt][nt][0] + b0, 0.f);
                float vy = fmaxf(acc[mt][nt][1] + b1, 0.f);
                *(float2*)&raw[(size_t)m0 * HID + n0] = make_float2(vx, vy);
                *(__half2*)&h[(size_t)m0 * HID + n0] = __floats2half2_rn(vx, vy);
                pa0 += vx * w10 + vy * w11;
                qa0 += vx * w20 + vy * w21;
            }
            if (m1 < n) {
                float vx = fmaxf(acc[mt][nt][2] + b0, 0.f);
                float vy = fmaxf(acc[mt][nt][3] + b1, 0.f);
                *(float2*)&raw[(size_t)m1 * HID + n0] = make_float2(vx, vy);
                *(__half2*)&h[(size_t)m1 * HID + n0] = __floats2half2_rn(vx, vy);
                pa1 += vx * w10 + vy * w11;
                qa1 += vx * w20 + vy * w21;
            }
        }
        atomicAdd(&sp[lm0], pa0); atomicAdd(&sq[lm0], qa0);
        atomicAdd(&sp[lm1], pa1); atomicAdd(&sq[lm1], qa1);
    }
    __syncthreads();
    if (tid < 64 && blockM + tid < n) {
        p0[blockM + tid] = sp[tid];
        q0[blockM + tid] = sq[tid];
    }
}

// ------- gathered SpMM per layer + fused next-layer gate dots (proven) ----
__global__ __launch_bounds__(256)
void k_agg(const __half* __restrict__ h, __half* __restrict__ hn,
           const float* __restrict__ gbp, int kidx,
           const float* __restrict__ p_in, const float* __restrict__ q_in,
           float* __restrict__ p_out, float* __restrict__ q_out,
           const float* __restrict__ gw_next) {
    int gt = blockIdx.x * blockDim.x + threadIdx.x;
    int warp = gt >> 5, lane = gt & 31;
    if (warp >= N_NODES) return;
    float gb = __ldg(&gbp[kidx]);
    int beg = g_indptr[warp], end = g_indptr[warp + 1];
    float qc = q_in[warp];
    float4 r = ((const float4*)g_raw)[warp * 32 + lane];
    float4 acc = make_float4(EPS_V * r.x, EPS_V * r.y, EPS_V * r.z, EPS_V * r.w);
    const uint2* h2 = (const uint2*)h;

    for (int e = beg; e < end; e += 32) {
        int idx = e + lane;
        int src = 0; float nrm = 0.f;
        if (idx < end) {
            src = g_esrc[idx];
            nrm = tanhf(p_in[src] + qc + gb) * g_ew[idx];
        }
        int m = end - e; if (m > 32) m = 32;
        int j = 0;
        for (; j + 4 <= m; j += 4) {
            int s0 = __shfl_sync(0xffffffffu, src, j + 0);
            int s1 = __shfl_sync(0xffffffffu, src, j + 1);
            int s2 = __shfl_sync(0xffffffffu, src, j + 2);
            int s3 = __shfl_sync(0xffffffffu, src, j + 3);
            float n0 = __shfl_sync(0xffffffffu, nrm, j + 0);
            float n1 = __shfl_sync(0xffffffffu, nrm, j + 1);
            float n2 = __shfl_sync(0xffffffffu, nrm, j + 2);
            float n3 = __shfl_sync(0xffffffffu, nrm, j + 3);
            uint2 v0 = h2[(size_t)s0 * 32 + lane];
            uint2 v1 = h2[(size_t)s1 * 32 + lane];
            uint2 v2 = h2[(size_t)s2 * 32 + lane];
            uint2 v3 = h2[(size_t)s3 * 32 + lane];
            float2 a0 = __half22float2(*(__half2*)&v0.x), b0 = __half22float2(*(__half2*)&v0.y);
            float2 a1 = __half22float2(*(__half2*)&v1.x), b1 = __half22float2(*(__half2*)&v1.y);
            float2 a2 = __half22float2(*(__half2*)&v2.x), b2 = __half22float2(*(__half2*)&v2.y);
            float2 a3 = __half22float2(*(__half2*)&v3.x), b3 = __half22float2(*(__half2*)&v3.y);
            acc.x = fmaf(n0, a0.x, acc.x); acc.y = fmaf(n0, a0.y, acc.y);
            acc.z = fmaf(n0, b0.x, acc.z); acc.w = fmaf(n0, b0.y, acc.w);
            acc.x = fmaf(n1, a1.x, acc.x); acc.y = fmaf(n1, a1.y, acc.y);
            acc.z = fmaf(n1, b1.x, acc.z); acc.w = fmaf(n1, b1.y, acc.w);
            acc.x = fmaf(n2, a2.x, acc.x); acc.y = fmaf(n2, a2.y, acc.y);
            acc.z = fmaf(n2, b2.x, acc.z); acc.w = fmaf(n2, b2.y, acc.w);
            acc.x = fmaf(n3, a3.x, acc.x); acc.y = fmaf(n3, a3.y, acc.y);
            acc.z = fmaf(n3, b3.x, acc.z); acc.w = fmaf(n3, b3.y, acc.w);
        }
        for (; j < m; j++) {
            int   s  = __shfl_sync(0xffffffffu, src, j);
            float nm = __shfl_sync(0xffffffffu, nrm, j);
            uint2 hv = h2[(size_t)s * 32 + lane];
            float2 f01 = __half22float2(*(__half2*)&hv.x);
            float2 f23 = __half22float2(*(__half2*)&hv.y);
            acc.x = fmaf(nm, f01.x, acc.x);
            acc.y = fmaf(nm, f01.y, acc.y);
            acc.z = fmaf(nm, f23.x, acc.z);
            acc.w = fmaf(nm, f23.y, acc.w);
        }
    }
    uint2 packed;
    *(__half2*)&packed.x = __floats2half2_rn(acc.x, acc.y);
    *(__half2*)&packed.y = __floats2half2_rn(acc.z, acc.w);
    ((uint2*)hn)[warp * 32 + lane] = packed;

    if (gw_next) {
        float4 w1 = ((const float4*)gw_next)[lane];
        float4 w2 = ((const float4*)gw_next)[32 + lane];
        float a = acc.x * w1.x + acc.y * w1.y + acc.z * w1.z + acc.w * w1.w;
        float b = acc.x * w2.x + acc.y * w2.y + acc.z * w2.z + acc.w * w2.w;
        #pragma unroll
        for (int o = 16; o > 0; o >>= 1) {
            a += __shfl_down_sync(0xffffffffu, a, o);
            b += __shfl_down_sync(0xffffffffu, b, o);
        }
        if (lane == 0) { p_out[warp] = a; q_out[warp] = b; }
    }
}

// ------- 4th layer + fused per-warp classifier + log_softmax --------------
__global__ __launch_bounds__(256)
void k_agg_out(const __half* __restrict__ h,
               const float* __restrict__ gbp, int kidx,
               const float* __restrict__ p_in, const float* __restrict__ q_in,
               const float* __restrict__ t2w, const float* __restrict__ t2b,
               float* __restrict__ out) {
    __shared__ float sh[8][HID];    // 4 KB: per-warp staged h row
    int gt = blockIdx.x * blockDim.x + threadIdx.x;
    int warp = gt >> 5, lane = gt & 31;
    int wib = threadIdx.x >> 5;
    if (warp >= N_NODES) return;
    float gb = __ldg(&gbp[kidx]);
    int beg = g_indptr[warp], end = g_indptr[warp + 1];
    float qc = q_in[warp];
    float4 r = ((const float4*)g_raw)[warp * 32 + lane];
    float4 acc = make_float4(EPS_V * r.x, EPS_V * r.y, EPS_V * r.z, EPS_V * r.w);
    const uint2* h2 = (const uint2*)h;

    for (int e = beg; e < end; e += 32) {
        int idx = e + lane;
        int src = 0; float nrm = 0.f;
        if (idx < end) {
            src = g_esrc[idx];
            nrm = tanhf(p_in[src] + qc + gb) * g_ew[idx];
        }
        int m = end - e; if (m > 32) m = 32;
        int j = 0;
        for (; j + 4 <= m; j += 4) {
            int s0 = __shfl_sync(0xffffffffu, src, j + 0);
            int s1 = __shfl_sync(0xffffffffu, src, j + 1);
            int s2 = __shfl_sync(0xffffffffu, src, j + 2);
            int s3 = __shfl_sync(0xffffffffu, src, j + 3);
            float n0 = __shfl_sync(0xffffffffu, nrm, j + 0);
            float n1 = __shfl_sync(0xffffffffu, nrm, j + 1);
            float n2 = __shfl_sync(0xffffffffu, nrm, j + 2);
            float n3 = __shfl_sync(0xffffffffu, nrm, j + 3);
            uint2 v0 = h2[(size_t)s0 * 32 + lane];
            uint2 v1 = h2[(size_t)s1 * 32 + lane];
            uint2 v2 = h2[(size_t)s2 * 32 + lane];
            uint2 v3 = h2[(size_t)s3 * 32 + lane];
            float2 a0 = __half22float2(*(__half2*)&v0.x), b0 = __half22float2(*(__half2*)&v0.y);
            float2 a1 = __half22float2(*(__half2*)&v1.x), b1 = __half22float2(*(__half2*)&v1.y);
            float2 a2 = __half22float2(*(__half2*)&v2.x), b2 = __half22float2(*(__half2*)&v2.y);
            float2 a3 = __half22float2(*(__half2*)&v3.x), b3 = __half22float2(*(__half2*)&v3.y);
            acc.x = fmaf(n0, a0.x, acc.x); acc.y = fmaf(n0, a0.y, acc.y);
            acc.z = fmaf(n0, b0.x, acc.z); acc.w = fmaf(n0, b0.y, acc.w);
            acc.x = fmaf(n1, a1.x, acc.x); acc.y = fmaf(n1, a1.y, acc.y);
            acc.z = fmaf(n1, b1.x, acc.z); acc.w = fmaf(n1, b1.y, acc.w);
            acc.x = fmaf(n2, a2.x, acc.x); acc.y = fmaf(n2, a2.y, acc.y);
            acc.z = fmaf(n2, b2.x, acc.z); acc.w = fmaf(n2, b2.y, acc.w);
            acc.x = fmaf(n3, a3.x, acc.x); acc.y = fmaf(n3, a3.y, acc.y);
            acc.z = fmaf(n3, b3.x, acc.z); acc.w = fmaf(n3, b3.y, acc.w);
        }
        for (; j < m; j++) {
            int   s  = __shfl_sync(0xffffffffu, src, j);
            float nm = __shfl_sync(0xffffffffu, nrm, j);
            uint2 hv = h2[(size_t)s * 32 + lane];
            float2 f01 = __half22float2(*(__half2*)&hv.x);
            float2 f23 = __half22float2(*(__half2*)&hv.y);
            acc.x = fmaf(nm, f01.x, acc.x);
            acc.y = fmaf(nm, f01.y, acc.y);
            acc.z = fmaf(nm, f23.x, acc.z);
            acc.w = fmaf(nm, f23.y, acc.w);
        }
    }

    // ---- fused classifier: stage h row to smem, lanes compute logits ----
    ((float4*)sh[wib])[lane] = acc;
    __syncwarp();

    int c0 = lane;                         // classes 0..31
    int c1 = 32 + lane;                    // classes 32..39 (lane<8)
    bool has1 = (lane < 8);
    float l0 = __ldg(&t2b[c0]);
    float l1 = has1 ? __ldg(&t2b[c1]) : -1e30f;
    const float4* w0p = (const float4*)&t2w[(size_t)c0 * HID];
    const float4* w1p = has1 ? (const float4*)&t2w[(size_t)c1 * HID] : w0p;
    const float4* hp = (const float4*)sh[wib];
    #pragma unroll
    for (int k = 0; k < HID / 4; k++) {
        float4 hv = hp[k];
        float4 wa = __ldg(&w0p[k]);
        l0 = fmaf(hv.x, wa.x, l0); l0 = fmaf(hv.y, wa.y, l0);
        l0 = fmaf(hv.z, wa.z, l0); l0 = fmaf(hv.w, wa.w, l0);
        if (has1) {
            float4 wb = __ldg(&w1p[k]);
            l1 = fmaf(hv.x, wb.x, l1); l1 = fmaf(hv.y, wb.y, l1);
            l1 = fmaf(hv.z, wb.z, l1); l1 = fmaf(hv.w, wb.w, l1);
        }
    }
    // warp-wide max
    float mx = fmaxf(l0, l1);
    #pragma unroll
    for (int o = 16; o > 0; o >>= 1)
        mx = fmaxf(mx, __shfl_xor_sync(0xffffffffu, mx, o));
    // warp-wide sum of exp
    float sum = expf(l0 - mx) + (has1 ? expf(l1 - mx) : 0.f);
    #pragma unroll
    for (int o = 16; o > 0; o >>= 1)
        sum += __shfl_xor_sync(0xffffffffu, sum, o);
    float lse = mx + logf(sum);

    out[(size_t)warp * N_CLS + c0] = l0 - lse;
    if (has1) out[(size_t)warp * N_CLS + c1] = l1 - lse;
}

// ---------------- host launcher: fork/join, 7 launches --------------------
extern "C" void kernel_launch(void* const* d_in, const int* in_sizes, int n_in,
                              void* d_out, int out_size) {
    const float* x   = (const float*)d_in[0];
    const int*   ei  = (const int*)d_in[1];
    const float* t1w = (const float*)d_in[2];
    const float* t1b = (const float*)d_in[3];
    const float* gw  = (const float*)d_in[4];
    const float* gb  = (const float*)d_in[5];
    const float* t2w = (const float*)d_in[6];
    const float* t2b = (const float*)d_in[7];
    float* out = (float*)d_out;

    const int* row = ei;
    const int* col = ei + N_EDGES;

    __half *hA, *hB;
    float *raw, *pA, *qA, *pB, *qB;
    cudaGetSymbolAddress((void**)&hA,  g_hA);
    cudaGetSymbolAddress((void**)&hB,  g_hB);
    cudaGetSymbolAddress((void**)&raw, g_raw);
    cudaGetSymbolAddress((void**)&pA,  g_pA);
    cudaGetSymbolAddress((void**)&qA,  g_qA);
    cudaGetSymbolAddress((void**)&pB,  g_pB);
    cudaGetSymbolAddress((void**)&qB,  g_qB);

    static cudaStream_t s_side = 0;
    static cudaEvent_t  e_fork = 0, e_join = 0;
    static bool inited = false;
    if (!inited) {
        cudaStreamCreateWithFlags(&s_side, cudaStreamNonBlocking);
        cudaEventCreateWithFlags(&e_fork, cudaEventDisableTiming);
        cudaEventCreateWithFlags(&e_join, cudaEventDisableTiming);
        cudaFuncSetAttribute(k_gemm1_mma, cudaFuncAttributeMaxDynamicSharedMemorySize, GEMM_SMEM);
        inited = true;
    }

    int warpBlocks = (N_NODES * 32 + 255) / 256;

    k_init<<<(HID * F_INN + 255) / 256, 256>>>(t1w);
    cudaEventRecord(e_fork, 0);
    cudaStreamWaitEvent(s_side, e_fork, 0);

    // side stream: CSR build in ONE persistent kernel
    k_csr<<<CGRID, 256, 0, s_side>>>(row, col);
    cudaEventRecord(e_join, s_side);

    // main stream: GEMM (concurrent with CSR)
    k_gemm1_mma<<<(N_NODES + 63) / 64, 256, GEMM_SMEM>>>(x, t1b, gw, hA, raw, pA, qA, N_NODES);

    cudaStreamWaitEvent(0, e_join, 0);

    // layers 0-2: separate k_agg (proven fast)
    k_agg<<<warpBlocks, 256>>>(hA, hB, gb, 0, pA, qA, pB, qB, gw + 1 * 2 * HID);
    k_agg<<<warpBlocks, 256>>>(hB, hA, gb, 1, pB, qB, pA, qA, gw + 2 * 2 * HID);
    k_agg<<<warpBlocks, 256>>>(hA, hB, gb, 2, pA, qA, pB, qB, gw + 3 * 2 * HID);

    // layer 3 + classifier + log_softmax fused
    k_agg_out<<<warpBlocks, 256>>>(hB, gb, 3, pB, qB, t2w, t2b, out);
}

// round 15
// speedup vs baseline: 1.1214x; 1.0530x over previous
#include <cuda_runtime.h>
#include <cuda_bf16.h>
#include <cuda_fp16.h>
#include <math.h>
#include <stdint.h>

#define N_NODES 50000
#define N_EDGES 800000
#define F_INN   512
#define HID     128
#define N_CLS   40
#define EPS_V   0.3f

#define CGRID   196

// ---------------- scratch (static device globals; no allocations) ----------
__device__ float  g_raw[N_NODES * HID];
__device__ __half g_hA [N_NODES * HID];
__device__ __half g_hB [N_NODES * HID];
__device__ float  g_pA [N_NODES];
__device__ float  g_qA [N_NODES];
__device__ float  g_pB [N_NODES];
__device__ float  g_qB [N_NODES];
__device__ float  g_nd [N_NODES];
__device__ float  g_ew [N_EDGES];
__device__ int    g_esrc[N_EDGES];
__device__ int    g_indptr[N_NODES + 1];
__device__ int    g_cnt[N_NODES];
__device__ int    g_deg[N_NODES];
__device__ int    g_cursor[N_NODES];
__device__ int    g_bsum[256];
__device__ int    g_boff[256];
__device__ int    g_bars[4];
__device__ uint16_t g_whi[HID * F_INN];
__device__ uint16_t g_wlo[HID * F_INN];

// ================= PTX helpers (baseline sm_80+/sm_90 PTX only) ===========
__device__ __forceinline__ uint32_t smem_u32(const void* p) {
    uint32_t a;
    asm("{ .reg .u64 t; cvta.to.shared.u64 t, %1; cvt.u32.u64 %0, t; }" : "=r"(a) : "l"(p));
    return a;
}
__device__ __forceinline__ void ldsm_x4(uint32_t (&r)[4], uint32_t addr) {
    asm volatile("ldmatrix.sync.aligned.m8n8.x4.shared.b16 {%0,%1,%2,%3}, [%4];"
        : "=r"(r[0]), "=r"(r[1]), "=r"(r[2]), "=r"(r[3]) : "r"(addr));
}
__device__ __forceinline__ void ldsm_x2(uint32_t (&r)[2], uint32_t addr) {
    asm volatile("ldmatrix.sync.aligned.m8n8.x2.shared.b16 {%0,%1}, [%2];"
        : "=r"(r[0]), "=r"(r[1]) : "r"(addr));
}
__device__ __forceinline__ void mma_bf16(float (&d)[4], const uint32_t (&a)[4], const uint32_t (&b)[2]) {
    asm volatile("mma.sync.aligned.m16n8k16.row.col.f32.bf16.bf16.f32 "
        "{%0,%1,%2,%3}, {%4,%5,%6,%7}, {%8,%9}, {%0,%1,%2,%3};"
        : "+f"(d[0]), "+f"(d[1]), "+f"(d[2]), "+f"(d[3])
        : "r"(a[0]), "r"(a[1]), "r"(a[2]), "r"(a[3]), "r"(b[0]), "r"(b[1]));
}
__device__ __forceinline__ void cp_async16(uint32_t saddr, const void* gaddr) {
    asm volatile("cp.async.cg.shared.global [%0], [%1], 16;" :: "r"(saddr), "l"(gaddr));
}
#define CP_COMMIT() asm volatile("cp.async.commit_group;" ::: "memory")
#define CP_WAIT(N)  asm volatile("cp.async.wait_group %0;" :: "n"(N) : "memory")

// PDL primitives (sm_90+ baseline; GRIDDEPCONTROL in SASS)
__device__ __forceinline__ void pdl_wait() {
    asm volatile("griddepcontrol.wait;" ::: "memory");
}
__device__ __forceinline__ void pdl_trigger() {
    asm volatile("griddepcontrol.launch_dependents;" ::: "memory");
}

__device__ __forceinline__ uint32_t pack_bf16lo(float x, float y) {
    __nv_bfloat162 t = __floats2bfloat162_rn(x, y);
    return *reinterpret_cast<uint32_t*>(&t);
}

// monotonic grid barrier (k_csr only)
__device__ __forceinline__ void bar_mono(int* ctr, int target) {
    __syncthreads();
    if (threadIdx.x == 0) {
        __threadfence();
        atomicAdd(ctr, 1);
        while (*(volatile int*)ctr < target) { __nanosleep(64); }
    }
    __syncthreads();
}

// ---------------- k_init: W split + counter/barrier reset -----------------
__global__ void k_init(const float* __restrict__ W) {
    int i = blockIdx.x * 256 + threadIdx.x;
    if (i < HID * F_INN) {
        float w = W[i];
        uint32_t b = __float_as_uint(w);
        float h = __uint_as_float(b & 0xFFFF0000u);
        g_whi[i] = (uint16_t)(b >> 16);
        __nv_bfloat16 lo = __float2bfloat16(w - h);
        g_wlo[i] = *reinterpret_cast<uint16_t*>(&lo);
    }
    if (i < N_NODES) { g_cnt[i] = 0; g_deg[i] = 0; }
    if (i < 4) g_bars[i] = 0;
}

// ================= persistent CSR kernel (one launch; proven) ==============
__global__ __launch_bounds__(256, 2)
void k_csr(const int* __restrict__ row, const int* __restrict__ col) {
    __shared__ int s[256];
    int tid = threadIdx.x;
    int gtid = blockIdx.x * 256 + tid;
    const int NT = CGRID * 256;

    for (int e = gtid; e < N_EDGES; e += NT) {
        atomicAdd(&g_deg[row[e]], 1);
        atomicAdd(&g_cnt[col[e]], 1);
    }
    bar_mono(&g_bars[0], 1 * CGRID);

    {
        int i = gtid;
        int v = (i < N_NODES) ? g_cnt[i] : 0;
        s[tid] = v;
        __syncthreads();
        #pragma unroll
        for (int off = 1; off < 256; off <<= 1) {
            int t = (tid >= off) ? s[tid - off] : 0;
            __syncthreads();
            s[tid] += t;
            __syncthreads();
        }
        if (i < N_NODES) g_indptr[i] = s[tid] - v;
        if (tid == 255) g_bsum[blockIdx.x] = s[255];
    }
    bar_mono(&g_bars[0], 2 * CGRID);

    if (blockIdx.x == 0) {
        int v = (tid < CGRID) ? g_bsum[tid] : 0;
        s[tid] = v;
        __syncthreads();
        #pragma unroll
        for (int off = 1; off < 256; off <<= 1) {
            int t = (tid >= off) ? s[tid - off] : 0;
            __syncthreads();
            s[tid] += t;
            __syncthreads();
        }
        g_boff[tid] = s[tid] - v;
        if (tid == 0) g_indptr[N_NODES] = N_EDGES;
    }
    bar_mono(&g_bars[0], 3 * CGRID);

    for (int i = gtid; i < N_NODES; i += NT) {
        int ip = g_indptr[i] + g_boff[i >> 8];
        g_indptr[i] = ip;
        g_cursor[i] = ip;
        int d = g_deg[i];
        g_nd[i] = rsqrtf((float)(d < 1 ? 1 : d));
    }
    bar_mono(&g_bars[0], 4 * CGRID);

    for (int e = gtid; e < N_EDGES; e += NT) {
        int r = row[e], c = col[e];
        int pos = atomicAdd(&g_cursor[c], 1);
        g_esrc[pos] = r;
        g_ew[pos] = g_nd[r] * g_nd[c];
    }
}

// ============ GEMM1 (proven 88us): 64x128, cp.async W, fused L0 pq =========
#define TSTRIDE 40
#define SM_AS(buf)   ((buf) * 10240)
#define SM_WS(buf)   (20480 + (buf) * 20480)
#define SM_BIAS      61440
#define GEMM_SMEM    61952

__global__ __launch_bounds__(256, 2)
void k_gemm1_mma(const float* __restrict__ A, const float* __restrict__ bias,
                 const float* __restrict__ gw0,
                 __half* __restrict__ h, float* __restrict__ raw,
                 float* __restrict__ p0, float* __restrict__ q0, int n) {
    extern __shared__ char smem[];
    uint32_t sb = smem_u32(smem);
    float* sbias = (float*)(smem + SM_BIAS);
    __shared__ float sp[64], sq[64];

    pdl_wait();   // predecessor (k_init) writes g_whi/g_wlo

    int tid = threadIdx.x;
    int wid = tid >> 5, lane = tid & 31;
    int wm = (wid >> 2) * 32;
    int wn = (wid & 3) * 32;
    int blockM = blockIdx.x * 64;

    if (tid < HID) sbias[tid] = bias[tid];
    if (tid < 64) { sp[tid] = 0.f; sq[tid] = 0.f; }

    float acc[2][4][4];
    #pragma unroll
    for (int i = 0; i < 2; i++)
        #pragma unroll
        for (int j = 0; j < 4; j++)
            #pragma unroll
            for (int k = 0; k < 4; k++) acc[i][j][k] = 0.f;

    int lr  = tid >> 3;
    int lc4 = (tid & 7) * 4;
    int a_row = lane & 15, a_kh = (lane >> 4) * 8;
    int b_row = lane & 7,  b_kh = ((lane >> 3) & 1) * 8;

    float4 aReg[2];

    #pragma unroll
    for (int it = 0; it < 2; it++) {
        int gr = blockM + lr + it * 32;
        aReg[it] = (gr < n) ? *(const float4*)&A[(size_t)gr * F_INN + lc4]
                            : make_float4(0.f, 0.f, 0.f, 0.f);
    }
    #pragma unroll
    for (int it = 0; it < 2; it++) {
        int row = lr + it * 32;
        int boff = SM_AS(0) + (row * TSTRIDE + lc4) * 2;
        float4 av = aReg[it];
        uint32_t bx = __float_as_uint(av.x), by = __float_as_uint(av.y);
        uint32_t bz = __float_as_uint(av.z), bw = __float_as_uint(av.w);
        *(uint2*)(smem + boff) = make_uint2(__byte_perm(bx, by, 0x7632),
                                            __byte_perm(bz, bw, 0x7632));
        float lx = av.x - __uint_as_float(bx & 0xFFFF0000u);
        float ly = av.y - __uint_as_float(by & 0xFFFF0000u);
        float lz = av.z - __uint_as_float(bz & 0xFFFF0000u);
        float lw = av.w - __uint_as_float(bw & 0xFFFF0000u);
        *(uint2*)(smem + boff + 5120) = make_uint2(pack_bf16lo(lx, ly), pack_bf16lo(lz, lw));
    }
    #pragma unroll
    for (int it = 0; it < 2; it++) {
        int idx = tid + it * 256;
        int row = idx >> 2, seg = idx & 3;
        uint32_t dst = sb + SM_WS(0) + (row * TSTRIDE + seg * 8) * 2;
        cp_async16(dst,         &g_whi[row * F_INN + 0 + seg * 8]);
        cp_async16(dst + 10240, &g_wlo[row * F_INN + 0 + seg * 8]);
    }
    CP_COMMIT();
    #pragma unroll
    for (int it = 0; it < 2; it++) {
        int gr = blockM + lr + it * 32;
        aReg[it] = (gr < n) ? *(const float4*)&A[(size_t)gr * F_INN + 32 + lc4]
                            : make_float4(0.f, 0.f, 0.f, 0.f);
    }
    #pragma unroll
    for (int it = 0; it < 2; it++) {
        int idx = tid + it * 256;
        int row = idx >> 2, seg = idx & 3;
        uint32_t dst = sb + SM_WS(1) + (row * TSTRIDE + seg * 8) * 2;
        cp_async16(dst,         &g_whi[row * F_INN + 32 + seg * 8]);
        cp_async16(dst + 10240, &g_wlo[row * F_INN + 32 + seg * 8]);
    }
    CP_COMMIT();
    CP_WAIT(1);
    __syncthreads();

    for (int ch = 0; ch < 16; ch++) {
        int cur = ch & 1;
        uint32_t aBase = sb + SM_AS(cur);
        uint32_t wBase = sb + SM_WS(cur);

        if (ch + 1 < 16) {
            #pragma unroll
            for (int it = 0; it < 2; it++) {
                int row = lr + it * 32;
                int boff = SM_AS(cur ^ 1) + (row * TSTRIDE + lc4) * 2;
                float4 av = aReg[it];
                uint32_t bx = __float_as_uint(av.x), by = __float_as_uint(av.y);
                uint32_t bz = __float_as_uint(av.z), bw = __float_as_uint(av.w);
                *(uint2*)(smem + boff) = make_uint2(__byte_perm(bx, by, 0x7632),
                                                    __byte_perm(bz, bw, 0x7632));
                float lx = av.x - __uint_as_float(bx & 0xFFFF0000u);
                float ly = av.y - __uint_as_float(by & 0xFFFF0000u);
                float lz = av.z - __uint_as_float(bz & 0xFFFF0000u);
                float lw = av.w - __uint_as_float(bw & 0xFFFF0000u);
                *(uint2*)(smem + boff + 5120) = make_uint2(pack_bf16lo(lx, ly), pack_bf16lo(lz, lw));
            }
            if (ch + 2 < 16) {
                int k0n = (ch + 2) * 32;
                #pragma unroll
                for (int it = 0; it < 2; it++) {
                    int gr = blockM + lr + it * 32;
                    aReg[it] = (gr < n) ? *(const float4*)&A[(size_t)gr * F_INN + k0n + lc4]
                                        : make_float4(0.f, 0.f, 0.f, 0.f);
                }
            }
        }

        #pragma unroll
        for (int kk = 0; kk < 32; kk += 16) {
            uint32_t ah[2][4], al[2][4];
            #pragma unroll
            for (int mt = 0; mt < 2; mt++) {
                uint32_t ao = aBase + ((wm + mt * 16 + a_row) * TSTRIDE + kk + a_kh) * 2;
                ldsm_x4(ah[mt], ao);
                ldsm_x4(al[mt], ao + 5120);
            }
            uint32_t bh[4][2], bl[4][2];
            #pragma unroll
            for (int nt = 0; nt < 4; nt++) {
                uint32_t bo = wBase + ((wn + nt * 8 + b_row) * TSTRIDE + kk + b_kh) * 2;
                ldsm_x2(bh[nt], bo);
                ldsm_x2(bl[nt], bo + 10240);
            }
            #pragma unroll
            for (int mt = 0; mt < 2; mt++)
                #pragma unroll
                for (int nt = 0; nt < 4; nt++) {
                    mma_bf16(acc[mt][nt], ah[mt], bh[nt]);
                    mma_bf16(acc[mt][nt], ah[mt], bl[nt]);
                    mma_bf16(acc[mt][nt], al[mt], bh[nt]);
                }
        }
        __syncthreads();

        if (ch + 2 < 16) {
            int k0n = (ch + 2) * 32;
            #pragma unroll
            for (int it = 0; it < 2; it++) {
                int idx = tid + it * 256;
                int row = idx >> 2, seg = idx & 3;
                uint32_t dst = sb + SM_WS(cur) + (row * TSTRIDE + seg * 8) * 2;
                cp_async16(dst,         &g_whi[row * F_INN + k0n + seg * 8]);
                cp_async16(dst + 10240, &g_wlo[row * F_INN + k0n + seg * 8]);
            }
            CP_COMMIT();
            CP_WAIT(1);
        } else {
            CP_WAIT(0);
        }
    }

    #pragma unroll
    for (int mt = 0; mt < 2; mt++) {
        int lm0 = wm + mt * 16 + (lane >> 2);
        int lm1 = lm0 + 8;
        int m0 = blockM + lm0, m1 = blockM + lm1;
        float pa0 = 0.f, qa0 = 0.f, pa1 = 0.f, qa1 = 0.f;
        #pragma unroll
        for (int nt = 0; nt < 4; nt++) {
            int n0 = wn + nt * 8 + 2 * (lane & 3);
            float b0 = sbias[n0], b1 = sbias[n0 + 1];
            float w10 = __ldg(&gw0[n0]),       w11 = __ldg(&gw0[n0 + 1]);
            float w20 = __ldg(&gw0[HID + n0]), w21 = __ldg(&gw0[HID + n0 + 1]);
            if (m0 < n) {
                float vx = fmaxf(acc[mt][nt][0] + b0, 0.f);
                float vy = fmaxf(acc[mt][nt][1] + b1, 0.f);
                *(float2*)&raw[(size_t)m0 * HID + n0] = make_float2(vx, vy);
                *(__half2*)&h[(size_t)m0 * HID + n0] = __floats2half2_rn(vx, vy);
                pa0 += vx * w10 + vy * w11;
                qa0 += vx * w20 + vy * w21;
            }
            if (m1 < n) {
                float vx = fmaxf(acc[mt][nt][2] + b0, 0.f);
                float vy = fmaxf(acc[mt][nt][3] + b1, 0.f);
                *(float2*)&raw[(size_t)m1 * HID + n0] = make_float2(vx, vy);
                *(__half2*)&h[(size_t)m1 * HID + n0] = __floats2half2_rn(vx, vy);
                pa1 += vx * w10 + vy * w11;
                qa1 += vx * w20 + vy * w21;
            }
        }
        atomicAdd(&sp[lm0], pa0); atomicAdd(&sq[lm0], qa0);
        atomicAdd(&sp[lm1], pa1); atomicAdd(&sq[lm1], qa1);
    }
    __syncthreads();
    if (tid < 64 && blockM + tid < n) {
        p0[blockM + tid] = sp[tid];
        q0[blockM + tid] = sq[tid];
    }
}

// ------- gathered SpMM per layer + fused next-layer gate dots (proven) ----
__global__ __launch_bounds__(256)
void k_agg(const __half* __restrict__ h, __half* __restrict__ hn,
           const float* __restrict__ gbp, int kidx,
           const float* __restrict__ p_in, const float* __restrict__ q_in,
           float* __restrict__ p_out, float* __restrict__ q_out,
           const float* __restrict__ gw_next) {
    pdl_wait();   // predecessor's h/p/q writes
    int gt = blockIdx.x * blockDim.x + threadIdx.x;
    int warp = gt >> 5, lane = gt & 31;
    if (warp >= N_NODES) { pdl_trigger(); return; }
    float gb = __ldg(&gbp[kidx]);
    int beg = g_indptr[warp], end = g_indptr[warp + 1];
    float qc = q_in[warp];
    float4 r = ((const float4*)g_raw)[warp * 32 + lane];
    float4 acc = make_float4(EPS_V * r.x, EPS_V * r.y, EPS_V * r.z, EPS_V * r.w);
    const uint2* h2 = (const uint2*)h;

    for (int e = beg; e < end; e += 32) {
        int idx = e + lane;
        int src = 0; float nrm = 0.f;
        if (idx < end) {
            src = g_esrc[idx];
            nrm = tanhf(p_in[src] + qc + gb) * g_ew[idx];
        }
        int m = end - e; if (m > 32) m = 32;
        int j = 0;
        for (; j + 4 <= m; j += 4) {
            int s0 = __shfl_sync(0xffffffffu, src, j + 0);
            int s1 = __shfl_sync(0xffffffffu, src, j + 1);
            int s2 = __shfl_sync(0xffffffffu, src, j + 2);
            int s3 = __shfl_sync(0xffffffffu, src, j + 3);
            float n0 = __shfl_sync(0xffffffffu, nrm, j + 0);
            float n1 = __shfl_sync(0xffffffffu, nrm, j + 1);
            float n2 = __shfl_sync(0xffffffffu, nrm, j + 2);
            float n3 = __shfl_sync(0xffffffffu, nrm, j + 3);
            uint2 v0 = h2[(size_t)s0 * 32 + lane];
            uint2 v1 = h2[(size_t)s1 * 32 + lane];
            uint2 v2 = h2[(size_t)s2 * 32 + lane];
            uint2 v3 = h2[(size_t)s3 * 32 + lane];
            float2 a0 = __half22float2(*(__half2*)&v0.x), b0 = __half22float2(*(__half2*)&v0.y);
            float2 a1 = __half22float2(*(__half2*)&v1.x), b1 = __half22float2(*(__half2*)&v1.y);
            float2 a2 = __half22float2(*(__half2*)&v2.x), b2 = __half22float2(*(__half2*)&v2.y);
            float2 a3 = __half22float2(*(__half2*)&v3.x), b3 = __half22float2(*(__half2*)&v3.y);
            acc.x = fmaf(n0, a0.x, acc.x); acc.y = fmaf(n0, a0.y, acc.y);
            acc.z = fmaf(n0, b0.x, acc.z); acc.w = fmaf(n0, b0.y, acc.w);
            acc.x = fmaf(n1, a1.x, acc.x); acc.y = fmaf(n1, a1.y, acc.y);
            acc.z = fmaf(n1, b1.x, acc.z); acc.w = fmaf(n1, b1.y, acc.w);
            acc.x = fmaf(n2, a2.x, acc.x); acc.y = fmaf(n2, a2.y, acc.y);
            acc.z = fmaf(n2, b2.x, acc.z); acc.w = fmaf(n2, b2.y, acc.w);
            acc.x = fmaf(n3, a3.x, acc.x); acc.y = fmaf(n3, a3.y, acc.y);
            acc.z = fmaf(n3, b3.x, acc.z); acc.w = fmaf(n3, b3.y, acc.w);
        }
        for (; j < m; j++) {
            int   s  = __shfl_sync(0xffffffffu, src, j);
            float nm = __shfl_sync(0xffffffffu, nrm, j);
            uint2 hv = h2[(size_t)s * 32 + lane];
            float2 f01 = __half22float2(*(__half2*)&hv.x);
            float2 f23 = __half22float2(*(__half2*)&hv.y);
            acc.x = fmaf(nm, f01.x, acc.x);
            acc.y = fmaf(nm, f01.y, acc.y);
            acc.z = fmaf(nm, f23.x, acc.z);
            acc.w = fmaf(nm, f23.y, acc.w);
        }
    }
    uint2 packed;
    *(__half2*)&packed.x = __floats2half2_rn(acc.x, acc.y);
    *(__half2*)&packed.y = __floats2half2_rn(acc.z, acc.w);
    ((uint2*)hn)[warp * 32 + lane] = packed;

    if (gw_next) {
        float4 w1 = ((const float4*)gw_next)[lane];
        float4 w2 = ((const float4*)gw_next)[32 + lane];
        float a = acc.x * w1.x + acc.y * w1.y + acc.z * w1.z + acc.w * w1.w;
        float b = acc.x * w2.x + acc.y * w2.y + acc.z * w2.z + acc.w * w2.w;
        #pragma unroll
        for (int o = 16; o > 0; o >>= 1) {
            a += __shfl_down_sync(0xffffffffu, a, o);
            b += __shfl_down_sync(0xffffffffu, b, o);
        }
        if (lane == 0) { p_out[warp] = a; q_out[warp] = b; }
    }
    pdl_trigger();
}

// ------- 4th layer + fused per-warp classifier + log_softmax --------------
__global__ __launch_bounds__(256)
void k_agg_out(const __half* __restrict__ h,
               const float* __restrict__ gbp, int kidx,
               const float* __restrict__ p_in, const float* __restrict__ q_in,
               const float* __restrict__ t2w, const float* __restrict__ t2b,
               float* __restrict__ out) {
    __shared__ float sh[8][HID];
    pdl_wait();
    int gt = blockIdx.x * blockDim.x + threadIdx.x;
    int warp = gt >> 5, lane = gt & 31;
    int wib = threadIdx.x >> 5;
    if (warp >= N_NODES) return;
    float gb = __ldg(&gbp[kidx]);
    int beg = g_indptr[warp], end = g_indptr[warp + 1];
    float qc = q_in[warp];
    float4 r = ((const float4*)g_raw)[warp * 32 + lane];
    float4 acc = make_float4(EPS_V * r.x, EPS_V * r.y, EPS_V * r.z, EPS_V * r.w);
    const uint2* h2 = (const uint2*)h;

    for (int e = beg; e < end; e += 32) {
        int idx = e + lane;
        int src = 0; float nrm = 0.f;
        if (idx < end) {
            src = g_esrc[idx];
            nrm = tanhf(p_in[src] + qc + gb) * g_ew[idx];
        }
        int m = end - e; if (m > 32) m = 32;
        int j = 0;
        for (; j + 4 <= m; j += 4) {
            int s0 = __shfl_sync(0xffffffffu, src, j + 0);
            int s1 = __shfl_sync(0xffffffffu, src, j + 1);
            int s2 = __shfl_sync(0xffffffffu, src, j + 2);
            int s3 = __shfl_sync(0xffffffffu, src, j + 3);
            float n0 = __shfl_sync(0xffffffffu, nrm, j + 0);
            float n1 = __shfl_sync(0xffffffffu, nrm, j + 1);
            float n2 = __shfl_sync(0xffffffffu, nrm, j + 2);
            float n3 = __shfl_sync(0xffffffffu, nrm, j + 3);
            uint2 v0 = h2[(size_t)s0 * 32 + lane];
            uint2 v1 = h2[(size_t)s1 * 32 + lane];
            uint2 v2 = h2[(size_t)s2 * 32 + lane];
            uint2 v3 = h2[(size_t)s3 * 32 + lane];
            float2 a0 = __half22float2(*(__half2*)&v0.x), b0 = __half22float2(*(__half2*)&v0.y);
            float2 a1 = __half22float2(*(__half2*)&v1.x), b1 = __half22float2(*(__half2*)&v1.y);
            float2 a2 = __half22float2(*(__half2*)&v2.x), b2 = __half22float2(*(__half2*)&v2.y);
            float2 a3 = __half22float2(*(__half2*)&v3.x), b3 = __half22float2(*(__half2*)&v3.y);
            acc.x = fmaf(n0, a0.x, acc.x); acc.y = fmaf(n0, a0.y, acc.y);
            acc.z = fmaf(n0, b0.x, acc.z); acc.w = fmaf(n0, b0.y, acc.w);
            acc.x = fmaf(n1, a1.x, acc.x); acc.y = fmaf(n1, a1.y, acc.y);
            acc.z = fmaf(n1, b1.x, acc.z); acc.w = fmaf(n1, b1.y, acc.w);
            acc.x = fmaf(n2, a2.x, acc.x); acc.y = fmaf(n2, a2.y, acc.y);
            acc.z = fmaf(n2, b2.x, acc.z); acc.w = fmaf(n2, b2.y, acc.w);
            acc.x = fmaf(n3, a3.x, acc.x); acc.y = fmaf(n3, a3.y, acc.y);
            acc.z = fmaf(n3, b3.x, acc.z); acc.w = fmaf(n3, b3.y, acc.w);
        }
        for (; j < m; j++) {
            int   s  = __shfl_sync(0xffffffffu, src, j);
            float nm = __shfl_sync(0xffffffffu, nrm, j);
            uint2 hv = h2[(size_t)s * 32 + lane];
            float2 f01 = __half22float2(*(__half2*)&hv.x);
            float2 f23 = __half22float2(*(__half2*)&hv.y);
            acc.x = fmaf(nm, f01.x, acc.x);
            acc.y = fmaf(nm, f01.y, acc.y);
            acc.z = fmaf(nm, f23.x, acc.z);
            acc.w = fmaf(nm, f23.y, acc.w);
        }
    }

    ((float4*)sh[wib])[lane] = acc;
    __syncwarp();

    int c0 = lane;
    int c1 = 32 + lane;
    bool has1 = (lane < 8);
    float l0 = __ldg(&t2b[c0]);
    float l1 = has1 ? __ldg(&t2b[c1]) : -1e30f;
    const float4* w0p = (const float4*)&t2w[(size_t)c0 * HID];
    const float4* w1p = has1 ? (const float4*)&t2w[(size_t)c1 * HID] : w0p;
    const float4* hp = (const float4*)sh[wib];
    #pragma unroll
    for (int k = 0; k < HID / 4; k++) {
        float4 hv = hp[k];
        float4 wa = __ldg(&w0p[k]);
        l0 = fmaf(hv.x, wa.x, l0); l0 = fmaf(hv.y, wa.y, l0);
        l0 = fmaf(hv.z, wa.z, l0); l0 = fmaf(hv.w, wa.w, l0);
        if (has1) {
            float4 wb = __ldg(&w1p[k]);
            l1 = fmaf(hv.x, wb.x, l1); l1 = fmaf(hv.y, wb.y, l1);
            l1 = fmaf(hv.z, wb.z, l1); l1 = fmaf(hv.w, wb.w, l1);
        }
    }
    float mx = fmaxf(l0, l1);
    #pragma unroll
    for (int o = 16; o > 0; o >>= 1)
        mx = fmaxf(mx, __shfl_xor_sync(0xffffffffu, mx, o));
    float sum = expf(l0 - mx) + (has1 ? expf(l1 - mx) : 0.f);
    #pragma unroll
    for (int o = 16; o > 0; o >>= 1)
        sum += __shfl_xor_sync(0xffffffffu, sum, o);
    float lse = mx + logf(sum);

    out[(size_t)warp * N_CLS + c0] = l0 - lse;
    if (has1) out[(size_t)warp * N_CLS + c1] = l1 - lse;
}

// ---------------- host launcher: fork/join + PDL chain --------------------
extern "C" void kernel_launch(void* const* d_in, const int* in_sizes, int n_in,
                              void* d_out, int out_size) {
    const float* x   = (const float*)d_in[0];
    const int*   ei  = (const int*)d_in[1];
    const float* t1w = (const float*)d_in[2];
    const float* t1b = (const float*)d_in[3];
    const float* gw  = (const float*)d_in[4];
    const float* gb  = (const float*)d_in[5];
    const float* t2w = (const float*)d_in[6];
    const float* t2b = (const float*)d_in[7];
    float* out = (float*)d_out;

    const int* row = ei;
    const int* col = ei + N_EDGES;

    __half *hA, *hB;
    float *raw, *pA, *qA, *pB, *qB;
    cudaGetSymbolAddress((void**)&hA,  g_hA);
    cudaGetSymbolAddress((void**)&hB,  g_hB);
    cudaGetSymbolAddress((void**)&raw, g_raw);
    cudaGetSymbolAddress((void**)&pA,  g_pA);
    cudaGetSymbolAddress((void**)&qA,  g_qA);
    cudaGetSymbolAddress((void**)&pB,  g_pB);
    cudaGetSymbolAddress((void**)&qB,  g_qB);

    static cudaStream_t s_side = 0;
    static cudaEvent_t  e_fork = 0, e_join = 0;
    static bool inited = false;
    if (!inited) {
        cudaStreamCreateWithFlags(&s_side, cudaStreamNonBlocking);
        cudaEventCreateWithFlags(&e_fork, cudaEventDisableTiming);
        cudaEventCreateWithFlags(&e_join, cudaEventDisableTiming);
        cudaFuncSetAttribute(k_gemm1_mma, cudaFuncAttributeMaxDynamicSharedMemorySize, GEMM_SMEM);
        inited = true;
    }

    int warpBlocks = (N_NODES * 32 + 255) / 256;

    // PDL launch config helper
    cudaLaunchAttribute pdlAttr;
    pdlAttr.id = cudaLaunchAttributeProgrammaticStreamSerialization;
    pdlAttr.val.programmaticStreamSerializationAllowed = 1;

    k_init<<<(HID * F_INN + 255) / 256, 256>>>(t1w);
    cudaEventRecord(e_fork, 0);
    cudaStreamWaitEvent(s_side, e_fork, 0);

    // side stream: CSR build in ONE persistent kernel
    k_csr<<<CGRID, 256, 0, s_side>>>(row, col);
    cudaEventRecord(e_join, s_side);

    // main stream: GEMM (PDL on init; concurrent with CSR)
    {
        cudaLaunchConfig_t cfg = {};
        cfg.gridDim = dim3((N_NODES + 63) / 64);
        cfg.blockDim = dim3(256);
        cfg.dynamicSmemBytes = GEMM_SMEM;
        cfg.stream = 0;
        cfg.attrs = &pdlAttr;
        cfg.numAttrs = 1;
        cudaLaunchKernelEx(&cfg, k_gemm1_mma, x, t1b, (const float*)gw, hA, raw, pA, qA, (int)N_NODES);
    }

    cudaStreamWaitEvent(0, e_join, 0);

    // layer 0: plain launch (follows event wait; PDL semantics unclear there)
    k_agg<<<warpBlocks, 256>>>(hA, hB, gb, 0, pA, qA, pB, qB, gw + 1 * 2 * HID);

    // layers 1-2 + final: PDL chain
    {
        cudaLaunchConfig_t cfg = {};
        cfg.gridDim = dim3(warpBlocks);
        cfg.blockDim = dim3(256);
        cfg.dynamicSmemBytes = 0;
        cfg.stream = 0;
        cfg.attrs = &pdlAttr;
        cfg.numAttrs = 1;
        cudaLaunchKernelEx(&cfg, k_agg, (const __half*)hB, hA, gb, 1,
                           (const float*)pB, (const float*)qB, pA, qA,
                           (const float*)(gw + 2 * 2 * HID));
        cudaLaunchKernelEx(&cfg, k_agg, (const __half*)hA, hB, gb, 2,
                           (const float*)pA, (const float*)qA, pB, qB,
                           (const float*)(gw + 3 * 2 * HID));
        cudaLaunchKernelEx(&cfg, k_agg_out, (const __half*)hB, gb, 3,
                           (const float*)pB, (const float*)qB, t2w, t2b, out);
    }
}

// round 16
// speedup vs baseline: 1.1225x; 1.0009x over previous
#include <cuda_runtime.h>
#include <cuda_bf16.h>
#include <cuda_fp16.h>
#include <math.h>
#include <stdint.h>

#define N_NODES 50000
#define N_EDGES 800000
#define F_INN   512
#define HID     128
#define N_CLS   40
#define EPS_V   0.3f

#define CGRID   196

// ---------------- scratch (static device globals; no allocations) ----------
__device__ float  g_raw[N_NODES * HID];
__device__ __half g_hA [N_NODES * HID];
__device__ __half g_hB [N_NODES * HID];
__device__ float  g_pA [N_NODES];
__device__ float  g_qA [N_NODES];
__device__ float  g_pB [N_NODES];
__device__ float  g_qB [N_NODES];
__device__ float  g_nd [N_NODES];
__device__ float  g_ew [N_EDGES];
__device__ int    g_esrc[N_EDGES];
__device__ int    g_indptr[N_NODES + 1];
__device__ int    g_cnt[N_NODES];
__device__ int    g_deg[N_NODES];
__device__ int    g_cursor[N_NODES];
__device__ int    g_bsum[256];
__device__ int    g_boff[256];
__device__ int    g_bars[4];
__device__ uint16_t g_whi[HID * F_INN];
__device__ uint16_t g_wlo[HID * F_INN];

// ================= PTX helpers (baseline sm_80+/sm_90 PTX only) ===========
__device__ __forceinline__ uint32_t smem_u32(const void* p) {
    uint32_t a;
    asm("{ .reg .u64 t; cvta.to.shared.u64 t, %1; cvt.u32.u64 %0, t; }" : "=r"(a) : "l"(p));
    return a;
}
__device__ __forceinline__ void ldsm_x4(uint32_t (&r)[4], uint32_t addr) {
    asm volatile("ldmatrix.sync.aligned.m8n8.x4.shared.b16 {%0,%1,%2,%3}, [%4];"
        : "=r"(r[0]), "=r"(r[1]), "=r"(r[2]), "=r"(r[3]) : "r"(addr));
}
__device__ __forceinline__ void ldsm_x2(uint32_t (&r)[2], uint32_t addr) {
    asm volatile("ldmatrix.sync.aligned.m8n8.x2.shared.b16 {%0,%1}, [%2];"
        : "=r"(r[0]), "=r"(r[1]) : "r"(addr));
}
__device__ __forceinline__ void mma_bf16(float (&d)[4], const uint32_t (&a)[4], const uint32_t (&b)[2]) {
    asm volatile("mma.sync.aligned.m16n8k16.row.col.f32.bf16.bf16.f32 "
        "{%0,%1,%2,%3}, {%4,%5,%6,%7}, {%8,%9}, {%0,%1,%2,%3};"
        : "+f"(d[0]), "+f"(d[1]), "+f"(d[2]), "+f"(d[3])
        : "r"(a[0]), "r"(a[1]), "r"(a[2]), "r"(a[3]), "r"(b[0]), "r"(b[1]));
}
__device__ __forceinline__ void cp_async16(uint32_t saddr, const void* gaddr) {
    asm volatile("cp.async.cg.shared.global [%0], [%1], 16;" :: "r"(saddr), "l"(gaddr));
}
#define CP_COMMIT() asm volatile("cp.async.commit_group;" ::: "memory")
#define CP_WAIT(N)  asm volatile("cp.async.wait_group %0;" :: "n"(N) : "memory")

// PDL primitives (sm_90+ baseline; GRIDDEPCONTROL in SASS)
__device__ __forceinline__ void pdl_wait() {
    asm volatile("griddepcontrol.wait;" ::: "memory");
}
__device__ __forceinline__ void pdl_trigger() {
    asm volatile("griddepcontrol.launch_dependents;" ::: "memory");
}

__device__ __forceinline__ uint32_t pack_bf16lo(float x, float y) {
    __nv_bfloat162 t = __floats2bfloat162_rn(x, y);
    return *reinterpret_cast<uint32_t*>(&t);
}

// monotonic grid barrier (k_csr only)
__device__ __forceinline__ void bar_mono(int* ctr, int target) {
    __syncthreads();
    if (threadIdx.x == 0) {
        __threadfence();
        atomicAdd(ctr, 1);
        while (*(volatile int*)ctr < target) { __nanosleep(64); }
    }
    __syncthreads();
}

// ---------------- k_init: W split + counter/barrier reset -----------------
__global__ void k_init(const float* __restrict__ W) {
    int i = blockIdx.x * 256 + threadIdx.x;
    if (i < HID * F_INN) {
        float w = W[i];
        uint32_t b = __float_as_uint(w);
        float h = __uint_as_float(b & 0xFFFF0000u);
        g_whi[i] = (uint16_t)(b >> 16);
        __nv_bfloat16 lo = __float2bfloat16(w - h);
        g_wlo[i] = *reinterpret_cast<uint16_t*>(&lo);
    }
    if (i < N_NODES) { g_cnt[i] = 0; g_deg[i] = 0; }
    if (i < 4) g_bars[i] = 0;
}

// ================= persistent CSR kernel (one launch; proven) ==============
__global__ __launch_bounds__(256, 2)
void k_csr(const int* __restrict__ row, const int* __restrict__ col) {
    __shared__ int s[256];
    int tid = threadIdx.x;
    int gtid = blockIdx.x * 256 + tid;
    const int NT = CGRID * 256;

    for (int e = gtid; e < N_EDGES; e += NT) {
        atomicAdd(&g_deg[row[e]], 1);
        atomicAdd(&g_cnt[col[e]], 1);
    }
    bar_mono(&g_bars[0], 1 * CGRID);

    {
        int i = gtid;
        int v = (i < N_NODES) ? g_cnt[i] : 0;
        s[tid] = v;
        __syncthreads();
        #pragma unroll
        for (int off = 1; off < 256; off <<= 1) {
            int t = (tid >= off) ? s[tid - off] : 0;
            __syncthreads();
            s[tid] += t;
            __syncthreads();
        }
        if (i < N_NODES) g_indptr[i] = s[tid] - v;
        if (tid == 255) g_bsum[blockIdx.x] = s[255];
    }
    bar_mono(&g_bars[0], 2 * CGRID);

    if (blockIdx.x == 0) {
        int v = (tid < CGRID) ? g_bsum[tid] : 0;
        s[tid] = v;
        __syncthreads();
        #pragma unroll
        for (int off = 1; off < 256; off <<= 1) {
            int t = (tid >= off) ? s[tid - off] : 0;
            __syncthreads();
            s[tid] += t;
            __syncthreads();
        }
        g_boff[tid] = s[tid] - v;
        if (tid == 0) g_indptr[N_NODES] = N_EDGES;
    }
    bar_mono(&g_bars[0], 3 * CGRID);

    for (int i = gtid; i < N_NODES; i += NT) {
        int ip = g_indptr[i] + g_boff[i >> 8];
        g_indptr[i] = ip;
        g_cursor[i] = ip;
        int d = g_deg[i];
        g_nd[i] = rsqrtf((float)(d < 1 ? 1 : d));
    }
    bar_mono(&g_bars[0], 4 * CGRID);

    for (int e = gtid; e < N_EDGES; e += NT) {
        int r = row[e], c = col[e];
        int pos = atomicAdd(&g_cursor[c], 1);
        g_esrc[pos] = r;
        g_ew[pos] = g_nd[r] * g_nd[c];
    }
}

// ============ GEMM1 (proven 88us): 64x128, cp.async W, fused L0 pq =========
#define TSTRIDE 40
#define SM_AS(buf)   ((buf) * 10240)
#define SM_WS(buf)   (20480 + (buf) * 20480)
#define SM_BIAS      61440
#define GEMM_SMEM    61952

__global__ __launch_bounds__(256, 2)
void k_gemm1_mma(const float* __restrict__ A, const float* __restrict__ bias,
                 const float* __restrict__ gw0,
                 __half* __restrict__ h, float* __restrict__ raw,
                 float* __restrict__ p0, float* __restrict__ q0, int n) {
    extern __shared__ char smem[];
    uint32_t sb = smem_u32(smem);
    float* sbias = (float*)(smem + SM_BIAS);
    __shared__ float sp[64], sq[64];

    pdl_wait();   // predecessor (k_init) writes g_whi/g_wlo

    int tid = threadIdx.x;
    int wid = tid >> 5, lane = tid & 31;
    int wm = (wid >> 2) * 32;
    int wn = (wid & 3) * 32;
    int blockM = blockIdx.x * 64;

    if (tid < HID) sbias[tid] = bias[tid];
    if (tid < 64) { sp[tid] = 0.f; sq[tid] = 0.f; }

    float acc[2][4][4];
    #pragma unroll
    for (int i = 0; i < 2; i++)
        #pragma unroll
        for (int j = 0; j < 4; j++)
            #pragma unroll
            for (int k = 0; k < 4; k++) acc[i][j][k] = 0.f;

    int lr  = tid >> 3;
    int lc4 = (tid & 7) * 4;
    int a_row = lane & 15, a_kh = (lane >> 4) * 8;
    int b_row = lane & 7,  b_kh = ((lane >> 3) & 1) * 8;

    float4 aReg[2];

    #pragma unroll
    for (int it = 0; it < 2; it++) {
        int gr = blockM + lr + it * 32;
        aReg[it] = (gr < n) ? *(const float4*)&A[(size_t)gr * F_INN + lc4]
                            : make_float4(0.f, 0.f, 0.f, 0.f);
    }
    #pragma unroll
    for (int it = 0; it < 2; it++) {
        int row = lr + it * 32;
        int boff = SM_AS(0) + (row * TSTRIDE + lc4) * 2;
        float4 av = aReg[it];
        uint32_t bx = __float_as_uint(av.x), by = __float_as_uint(av.y);
        uint32_t bz = __float_as_uint(av.z), bw = __float_as_uint(av.w);
        *(uint2*)(smem + boff) = make_uint2(__byte_perm(bx, by, 0x7632),
                                            __byte_perm(bz, bw, 0x7632));
        float lx = av.x - __uint_as_float(bx & 0xFFFF0000u);
        float ly = av.y - __uint_as_float(by & 0xFFFF0000u);
        float lz = av.z - __uint_as_float(bz & 0xFFFF0000u);
        float lw = av.w - __uint_as_float(bw & 0xFFFF0000u);
        *(uint2*)(smem + boff + 5120) = make_uint2(pack_bf16lo(lx, ly), pack_bf16lo(lz, lw));
    }
    #pragma unroll
    for (int it = 0; it < 2; it++) {
        int idx = tid + it * 256;
        int row = idx >> 2, seg = idx & 3;
        uint32_t dst = sb + SM_WS(0) + (row * TSTRIDE + seg * 8) * 2;
        cp_async16(dst,         &g_whi[row * F_INN + 0 + seg * 8]);
        cp_async16(dst + 10240, &g_wlo[row * F_INN + 0 + seg * 8]);
    }
    CP_COMMIT();
    #pragma unroll
    for (int it = 0; it < 2; it++) {
        int gr = blockM + lr + it * 32;
        aReg[it] = (gr < n) ? *(const float4*)&A[(size_t)gr * F_INN + 32 + lc4]
                            : make_float4(0.f, 0.f, 0.f, 0.f);
    }
    #pragma unroll
    for (int it = 0; it < 2; it++) {
        int idx = tid + it * 256;
        int row = idx >> 2, seg = idx & 3;
        uint32_t dst = sb + SM_WS(1) + (row * TSTRIDE + seg * 8) * 2;
        cp_async16(dst,         &g_whi[row * F_INN + 32 + seg * 8]);
        cp_async16(dst + 10240, &g_wlo[row * F_INN + 32 + seg * 8]);
    }
    CP_COMMIT();
    CP_WAIT(1);
    __syncthreads();

    for (int ch = 0; ch < 16; ch++) {
        int cur = ch & 1;
        uint32_t aBase = sb + SM_AS(cur);
        uint32_t wBase = sb + SM_WS(cur);

        if (ch + 1 < 16) {
            #pragma unroll
            for (int it = 0; it < 2; it++) {
                int row = lr + it * 32;
                int boff = SM_AS(cur ^ 1) + (row * TSTRIDE + lc4) * 2;
                float4 av = aReg[it];
                uint32_t bx = __float_as_uint(av.x), by = __float_as_uint(av.y);
                uint32_t bz = __float_as_uint(av.z), bw = __float_as_uint(av.w);
                *(uint2*)(smem + boff) = make_uint2(__byte_perm(bx, by, 0x7632),
                                                    __byte_perm(bz, bw, 0x7632));
                float lx = av.x - __uint_as_float(bx & 0xFFFF0000u);
                float ly = av.y - __uint_as_float(by & 0xFFFF0000u);
                float lz = av.z - __uint_as_float(bz & 0xFFFF0000u);
                float lw = av.w - __uint_as_float(bw & 0xFFFF0000u);
                *(uint2*)(smem + boff + 5120) = make_uint2(pack_bf16lo(lx, ly), pack_bf16lo(lz, lw));
            }
            if (ch + 2 < 16) {
                int k0n = (ch + 2) * 32;
                #pragma unroll
                for (int it = 0; it < 2; it++) {
                    int gr = blockM + lr + it * 32;
                    aReg[it] = (gr < n) ? *(const float4*)&A[(size_t)gr * F_INN + k0n + lc4]
                                        : make_float4(0.f, 0.f, 0.f, 0.f);
                }
            }
        }

        #pragma unroll
        for (int kk = 0; kk < 32; kk += 16) {
            uint32_t ah[2][4], al[2][4];
            #pragma unroll
            for (int mt = 0; mt < 2; mt++) {
                uint32_t ao = aBase + ((wm + mt * 16 + a_row) * TSTRIDE + kk + a_kh) * 2;
                ldsm_x4(ah[mt], ao);
                ldsm_x4(al[mt], ao + 5120);
            }
            uint32_t bh[4][2], bl[4][2];
            #pragma unroll
            for (int nt = 0; nt < 4; nt++) {
                uint32_t bo = wBase + ((wn + nt * 8 + b_row) * TSTRIDE + kk + b_kh) * 2;
                ldsm_x2(bh[nt], bo);
                ldsm_x2(bl[nt], bo + 10240);
            }
            #pragma unroll
            for (int mt = 0; mt < 2; mt++)
                #pragma unroll
                for (int nt = 0; nt < 4; nt++) {
                    mma_bf16(acc[mt][nt], ah[mt], bh[nt]);
                    mma_bf16(acc[mt][nt], ah[mt], bl[nt]);
                    mma_bf16(acc[mt][nt], al[mt], bh[nt]);
                }
        }
        __syncthreads();

        if (ch + 2 < 16) {
            int k0n = (ch + 2) * 32;
            #pragma unroll
            for (int it = 0; it < 2; it++) {
                int idx = tid + it * 256;
                int row = idx >> 2, seg = idx & 3;
                uint32_t dst = sb + SM_WS(cur) + (row * TSTRIDE + seg * 8) * 2;
                cp_async16(dst,         &g_whi[row * F_INN + k0n + seg * 8]);
                cp_async16(dst + 10240, &g_wlo[row * F_INN + k0n + seg * 8]);
            }
            CP_COMMIT();
            CP_WAIT(1);
        } else {
            CP_WAIT(0);
        }
    }

    #pragma unroll
    for (int mt = 0; mt < 2; mt++) {
        int lm0 = wm + mt * 16 + (lane >> 2);
        int lm1 = lm0 + 8;
        int m0 = blockM + lm0, m1 = blockM + lm1;
        float pa0 = 0.f, qa0 = 0.f, pa1 = 0.f, qa1 = 0.f;
        #pragma unroll
        for (int nt = 0; nt < 4; nt++) {
            int n0 = wn + nt * 8 + 2 * (lane & 3);
            float b0 = sbias[n0], b1 = sbias[n0 + 1];
            float w10 = __ldg(&gw0[n0]),       w11 = __ldg(&gw0[n0 + 1]);
            float w20 = __ldg(&gw0[HID + n0]), w21 = __ldg(&gw0[HID + n0 + 1]);
            if (m0 < n) {
                float vx = fmaxf(acc[mt][nt][0] + b0, 0.f);
                float vy = fmaxf(acc[mt][nt][1] + b1, 0.f);
                *(float2*)&raw[(size_t)m0 * HID + n0] = make_float2(vx, vy);
                *(__half2*)&h[(size_t)m0 * HID + n0] = __floats2half2_rn(vx, vy);
                pa0 += vx * w10 + vy * w11;
                qa0 += vx * w20 + vy * w21;
            }
            if (m1 < n) {
                float vx = fmaxf(acc[mt][nt][2] + b0, 0.f);
                float vy = fmaxf(acc[mt][nt][3] + b1, 0.f);
                *(float2*)&raw[(size_t)m1 * HID + n0] = make_float2(vx, vy);
                *(__half2*)&h[(size_t)m1 * HID + n0] = __floats2half2_rn(vx, vy);
                pa1 += vx * w10 + vy * w11;
                qa1 += vx * w20 + vy * w21;
            }
        }
        atomicAdd(&sp[lm0], pa0); atomicAdd(&sq[lm0], qa0);
        atomicAdd(&sp[lm1], pa1); atomicAdd(&sq[lm1], qa1);
    }
    __syncthreads();
    if (tid < 64 && blockM + tid < n) {
        p0[blockM + tid] = sp[tid];
        q0[blockM + tid] = sq[tid];
    }
    pdl_trigger();   // dependents (agg0) may launch now
}

// ------- gathered SpMM per layer + fused next-layer gate dots (proven) ----
__global__ __launch_bounds__(256)
void k_agg(const __half* __restrict__ h, __half* __restrict__ hn,
           const float* __restrict__ gbp, int kidx,
           const float* __restrict__ p_in, const float* __restrict__ q_in,
           float* __restrict__ p_out, float* __restrict__ q_out,
           const float* __restrict__ gw_next) {
    int gt = blockIdx.x * blockDim.x + threadIdx.x;
    int warp = gt >> 5, lane = gt & 31;
    if (warp >= N_NODES) { pdl_wait(); pdl_trigger(); return; }

    // CSR-sourced loads are safe before pdl_wait (k_csr completion is a
    // hard graph edge before agg0; layers>=1 trivially after)
    float gb = __ldg(&gbp[kidx]);
    int beg = g_indptr[warp], end = g_indptr[warp + 1];

    pdl_wait();   // predecessor's h/p/q/raw writes

    float qc = q_in[warp];
    float4 r = ((const float4*)g_raw)[warp * 32 + lane];
    float4 acc = make_float4(EPS_V * r.x, EPS_V * r.y, EPS_V * r.z, EPS_V * r.w);
    const uint2* h2 = (const uint2*)h;

    for (int e = beg; e < end; e += 32) {
        int idx = e + lane;
        int src = 0; float nrm = 0.f;
        if (idx < end) {
            src = g_esrc[idx];
            nrm = tanhf(p_in[src] + qc + gb) * g_ew[idx];
        }
        int m = end - e; if (m > 32) m = 32;
        int j = 0;
        for (; j + 4 <= m; j += 4) {
            int s0 = __shfl_sync(0xffffffffu, src, j + 0);
            int s1 = __shfl_sync(0xffffffffu, src, j + 1);
            int s2 = __shfl_sync(0xffffffffu, src, j + 2);
            int s3 = __shfl_sync(0xffffffffu, src, j + 3);
            float n0 = __shfl_sync(0xffffffffu, nrm, j + 0);
            float n1 = __shfl_sync(0xffffffffu, nrm, j + 1);
            float n2 = __shfl_sync(0xffffffffu, nrm, j + 2);
            float n3 = __shfl_sync(0xffffffffu, nrm, j + 3);
            uint2 v0 = h2[(size_t)s0 * 32 + lane];
            uint2 v1 = h2[(size_t)s1 * 32 + lane];
            uint2 v2 = h2[(size_t)s2 * 32 + lane];
            uint2 v3 = h2[(size_t)s3 * 32 + lane];
            float2 a0 = __half22float2(*(__half2*)&v0.x), b0 = __half22float2(*(__half2*)&v0.y);
            float2 a1 = __half22float2(*(__half2*)&v1.x), b1 = __half22float2(*(__half2*)&v1.y);
            float2 a2 = __half22float2(*(__half2*)&v2.x), b2 = __half22float2(*(__half2*)&v2.y);
            float2 a3 = __half22float2(*(__half2*)&v3.x), b3 = __half22float2(*(__half2*)&v3.y);
            acc.x = fmaf(n0, a0.x, acc.x); acc.y = fmaf(n0, a0.y, acc.y);
            acc.z = fmaf(n0, b0.x, acc.z); acc.w = fmaf(n0, b0.y, acc.w);
            acc.x = fmaf(n1, a1.x, acc.x); acc.y = fmaf(n1, a1.y, acc.y);
            acc.z = fmaf(n1, b1.x, acc.z); acc.w = fmaf(n1, b1.y, acc.w);
            acc.x = fmaf(n2, a2.x, acc.x); acc.y = fmaf(n2, a2.y, acc.y);
            acc.z = fmaf(n2, b2.x, acc.z); acc.w = fmaf(n2, b2.y, acc.w);
            acc.x = fmaf(n3, a3.x, acc.x); acc.y = fmaf(n3, a3.y, acc.y);
            acc.z = fmaf(n3, b3.x, acc.z); acc.w = fmaf(n3, b3.y, acc.w);
        }
        for (; j < m; j++) {
            int   s  = __shfl_sync(0xffffffffu, src, j);
            float nm = __shfl_sync(0xffffffffu, nrm, j);
            uint2 hv = h2[(size_t)s * 32 + lane];
            float2 f01 = __half22float2(*(__half2*)&hv.x);
            float2 f23 = __half22float2(*(__half2*)&hv.y);
            acc.x = fmaf(nm, f01.x, acc.x);
            acc.y = fmaf(nm, f01.y, acc.y);
            acc.z = fmaf(nm, f23.x, acc.z);
            acc.w = fmaf(nm, f23.y, acc.w);
        }
    }
    uint2 packed;
    *(__half2*)&packed.x = __floats2half2_rn(acc.x, acc.y);
    *(__half2*)&packed.y = __floats2half2_rn(acc.z, acc.w);
    ((uint2*)hn)[warp * 32 + lane] = packed;

    if (gw_next) {
        float4 w1 = ((const float4*)gw_next)[lane];
        float4 w2 = ((const float4*)gw_next)[32 + lane];
        float a = acc.x * w1.x + acc.y * w1.y + acc.z * w1.z + acc.w * w1.w;
        float b = acc.x * w2.x + acc.y * w2.y + acc.z * w2.z + acc.w * w2.w;
        #pragma unroll
        for (int o = 16; o > 0; o >>= 1) {
            a += __shfl_down_sync(0xffffffffu, a, o);
            b += __shfl_down_sync(0xffffffffu, b, o);
        }
        if (lane == 0) { p_out[warp] = a; q_out[warp] = b; }
    }
    pdl_trigger();
}

// ------- 4th layer + fused per-warp classifier + log_softmax --------------
__global__ __launch_bounds__(256)
void k_agg_out(const __half* __restrict__ h,
               const float* __restrict__ gbp, int kidx,
               const float* __restrict__ p_in, const float* __restrict__ q_in,
               const float* __restrict__ t2w, const float* __restrict__ t2b,
               float* __restrict__ out) {
    __shared__ float sh[8][HID];
    int gt = blockIdx.x * blockDim.x + threadIdx.x;
    int warp = gt >> 5, lane = gt & 31;
    int wib = threadIdx.x >> 5;
    if (warp >= N_NODES) { pdl_wait(); return; }

    float gb = __ldg(&gbp[kidx]);
    int beg = g_indptr[warp], end = g_indptr[warp + 1];

    pdl_wait();

    float qc = q_in[warp];
    float4 r = ((const float4*)g_raw)[warp * 32 + lane];
    float4 acc = make_float4(EPS_V * r.x, EPS_V * r.y, EPS_V * r.z, EPS_V * r.w);
    const uint2* h2 = (const uint2*)h;

    for (int e = beg; e < end; e += 32) {
        int idx = e + lane;
        int src = 0; float nrm = 0.f;
        if (idx < end) {
            src = g_esrc[idx];
            nrm = tanhf(p_in[src] + qc + gb) * g_ew[idx];
        }
        int m = end - e; if (m > 32) m = 32;
        int j = 0;
        for (; j + 4 <= m; j += 4) {
            int s0 = __shfl_sync(0xffffffffu, src, j + 0);
            int s1 = __shfl_sync(0xffffffffu, src, j + 1);
            int s2 = __shfl_sync(0xffffffffu, src, j + 2);
            int s3 = __shfl_sync(0xffffffffu, src, j + 3);
            float n0 = __shfl_sync(0xffffffffu, nrm, j + 0);
            float n1 = __shfl_sync(0xffffffffu, nrm, j + 1);
            float n2 = __shfl_sync(0xffffffffu, nrm, j + 2);
            float n3 = __shfl_sync(0xffffffffu, nrm, j + 3);
            uint2 v0 = h2[(size_t)s0 * 32 + lane];
            uint2 v1 = h2[(size_t)s1 * 32 + lane];
            uint2 v2 = h2[(size_t)s2 * 32 + lane];
            uint2 v3 = h2[(size_t)s3 * 32 + lane];
            float2 a0 = __half22float2(*(__half2*)&v0.x), b0 = __half22float2(*(__half2*)&v0.y);
            float2 a1 = __half22float2(*(__half2*)&v1.x), b1 = __half22float2(*(__half2*)&v1.y);
            float2 a2 = __half22float2(*(__half2*)&v2.x), b2 = __half22float2(*(__half2*)&v2.y);
            float2 a3 = __half22float2(*(__half2*)&v3.x), b3 = __half22float2(*(__half2*)&v3.y);
            acc.x = fmaf(n0, a0.x, acc.x); acc.y = fmaf(n0, a0.y, acc.y);
            acc.z = fmaf(n0, b0.x, acc.z); acc.w = fmaf(n0, b0.y, acc.w);
            acc.x = fmaf(n1, a1.x, acc.x); acc.y = fmaf(n1, a1.y, acc.y);
            acc.z = fmaf(n1, b1.x, acc.z); acc.w = fmaf(n1, b1.y, acc.w);
            acc.x = fmaf(n2, a2.x, acc.x); acc.y = fmaf(n2, a2.y, acc.y);
            acc.z = fmaf(n2, b2.x, acc.z); acc.w = fmaf(n2, b2.y, acc.w);
            acc.x = fmaf(n3, a3.x, acc.x); acc.y = fmaf(n3, a3.y, acc.y);
            acc.z = fmaf(n3, b3.x, acc.z); acc.w = fmaf(n3, b3.y, acc.w);
        }
        for (; j < m; j++) {
            int   s  = __shfl_sync(0xffffffffu, src, j);
            float nm = __shfl_sync(0xffffffffu, nrm, j);
            uint2 hv = h2[(size_t)s * 32 + lane];
            float2 f01 = __half22float2(*(__half2*)&hv.x);
            float2 f23 = __half22float2(*(__half2*)&hv.y);
            acc.x = fmaf(nm, f01.x, acc.x);
            acc.y = fmaf(nm, f01.y, acc.y);
            acc.z = fmaf(nm, f23.x, acc.z);
            acc.w = fmaf(nm, f23.y, acc.w);
        }
    }

    ((float4*)sh[wib])[lane] = acc;
    __syncwarp();

    int c0 = lane;
    int c1 = 32 + lane;
    bool has1 = (lane < 8);
    float l0 = __ldg(&t2b[c0]);
    float l1 = has1 ? __ldg(&t2b[c1]) : -1e30f;
    const float4* w0p = (const float4*)&t2w[(size_t)c0 * HID];
    const float4* w1p = has1 ? (const float4*)&t2w[(size_t)c1 * HID] : w0p;
    const float4* hp = (const float4*)sh[wib];
    #pragma unroll
    for (int k = 0; k < HID / 4; k++) {
        float4 hv = hp[k];
        float4 wa = __ldg(&w0p[k]);
        l0 = fmaf(hv.x, wa.x, l0); l0 = fmaf(hv.y, wa.y, l0);
        l0 = fmaf(hv.z, wa.z, l0); l0 = fmaf(hv.w, wa.w, l0);
        if (has1) {
            float4 wb = __ldg(&w1p[k]);
            l1 = fmaf(hv.x, wb.x, l1); l1 = fmaf(hv.y, wb.y, l1);
            l1 = fmaf(hv.z, wb.z, l1); l1 = fmaf(hv.w, wb.w, l1);
        }
    }
    float mx = fmaxf(l0, l1);
    #pragma unroll
    for (int o = 16; o > 0; o >>= 1)
        mx = fmaxf(mx, __shfl_xor_sync(0xffffffffu, mx, o));
    float sum = expf(l0 - mx) + (has1 ? expf(l1 - mx) : 0.f);
    #pragma unroll
    for (int o = 16; o > 0; o >>= 1)
        sum += __shfl_xor_sync(0xffffffffu, sum, o);
    float lse = mx + logf(sum);

    out[(size_t)warp * N_CLS + c0] = l0 - lse;
    if (has1) out[(size_t)warp * N_CLS + c1] = l1 - lse;
}

// ---------------- host launcher: fork/join + full PDL chain ---------------
extern "C" void kernel_launch(void* const* d_in, const int* in_sizes, int n_in,
                              void* d_out, int out_size) {
    const float* x   = (const float*)d_in[0];
    const int*   ei  = (const int*)d_in[1];
    const float* t1w = (const float*)d_in[2];
    const float* t1b = (const float*)d_in[3];
    const float* gw  = (const float*)d_in[4];
    const float* gb  = (const float*)d_in[5];
    const float* t2w = (const float*)d_in[6];
    const float* t2b = (const float*)d_in[7];
    float* out = (float*)d_out;

    const int* row = ei;
    const int* col = ei + N_EDGES;

    __half *hA, *hB;
    float *raw, *pA, *qA, *pB, *qB;
    cudaGetSymbolAddress((void**)&hA,  g_hA);
    cudaGetSymbolAddress((void**)&hB,  g_hB);
    cudaGetSymbolAddress((void**)&raw, g_raw);
    cudaGetSymbolAddress((void**)&pA,  g_pA);
    cudaGetSymbolAddress((void**)&qA,  g_qA);
    cudaGetSymbolAddress((void**)&pB,  g_pB);
    cudaGetSymbolAddress((void**)&qB,  g_qB);

    static cudaStream_t s_side = 0;
    static cudaEvent_t  e_fork = 0, e_join = 0;
    static bool inited = false;
    if (!inited) {
        cudaStreamCreateWithFlags(&s_side, cudaStreamNonBlocking);
        cudaEventCreateWithFlags(&e_fork, cudaEventDisableTiming);
        cudaEventCreateWithFlags(&e_join, cudaEventDisableTiming);
        cudaFuncSetAttribute(k_gemm1_mma, cudaFuncAttributeMaxDynamicSharedMemorySize, GEMM_SMEM);
        inited = true;
    }

    int warpBlocks = (N_NODES * 32 + 255) / 256;

    cudaLaunchAttribute pdlAttr;
    pdlAttr.id = cudaLaunchAttributeProgrammaticStreamSerialization;
    pdlAttr.val.programmaticStreamSerializationAllowed = 1;

    k_init<<<(HID * F_INN + 255) / 256, 256>>>(t1w);
    cudaEventRecord(e_fork, 0);
    cudaStreamWaitEvent(s_side, e_fork, 0);

    // side stream: CSR build in ONE persistent kernel
    k_csr<<<CGRID, 256, 0, s_side>>>(row, col);
    cudaEventRecord(e_join, s_side);

    // main stream: GEMM (PDL on init; concurrent with CSR)
    {
        cudaLaunchConfig_t cfg = {};
        cfg.gridDim = dim3((N_NODES + 63) / 64);
        cfg.blockDim = dim3(256);
        cfg.dynamicSmemBytes = GEMM_SMEM;
        cfg.stream = 0;
        cfg.attrs = &pdlAttr;
        cfg.numAttrs = 1;
        cudaLaunchKernelEx(&cfg, k_gemm1_mma, x, t1b, (const float*)gw, hA, raw, pA, qA, (int)N_NODES);
    }

    cudaStreamWaitEvent(0, e_join, 0);

    // all agg layers + final: PDL chain (agg0 also PDL'd on the GEMM edge)
    {
        cudaLaunchConfig_t cfg = {};
        cfg.gridDim = dim3(warpBlocks);
        cfg.blockDim = dim3(256);
        cfg.dynamicSmemBytes = 0;
        cfg.stream = 0;
        cfg.attrs = &pdlAttr;
        cfg.numAttrs = 1;
        cudaLaunchKernelEx(&cfg, k_agg, (const __half*)hA, hB, gb, 0,
                           (const float*)pA, (const float*)qA, pB, qB,
                           (const float*)(gw + 1 * 2 * HID));
        cudaLaunchKernelEx(&cfg, k_agg, (const __half*)hB, hA, gb, 1,
                           (const float*)pB, (const float*)qB, pA, qA,
                           (const float*)(gw + 2 * 2 * HID));
        cudaLaunchKernelEx(&cfg, k_agg, (const __half*)hA, hB, gb, 2,
                           (const float*)pA, (const float*)qA, pB, qB,
                           (const float*)(gw + 3 * 2 * HID));
        cudaLaunchKernelEx(&cfg, k_agg_out, (const __half*)hB, gb, 3,
                           (const float*)pB, (const float*)qB, t2w, t2b, out);
    }
}